// round 9
// baseline (speedup 1.0000x reference)
#include <cuda_runtime.h>
#include <math.h>

#define B_   2
#define T_   2048
#define C_   2048
#define H_   16
#define HS_  128
#define NLQ_ 512
#define NLKV_ 512
#define RHD_ 64
#define D_   192

// Scratch (allocation-free rule)
__device__ float g_cq [B_*T_*NLQ_];
__device__ float g_ckv[B_*T_*NLKV_];
__device__ float g_q  [B_*H_*T_*D_];    // tf32-pre-rounded
__device__ float g_k  [B_*H_*T_*D_];    // tf32-pre-rounded
__device__ float g_v  [B_*H_*T_*HS_];   // tf32-pre-rounded
__device__ float g_ao [B_*T_*C_];       // tf32-pre-rounded
__device__ float g_x  [B_*T_*C_];       // tf32-rounded copy of x
__device__ float g_w  [10092544];       // tf32-rounded concat of all weights

// float offsets into g_w
#define OFF_WDQ  0
#define OFF_WDKV 1048576
#define OFF_WKR  2097152
#define OFF_WUQ  2228224
#define OFF_WQR  3276800
#define OFF_WUK  3801088
#define OFF_WUV  4849664
#define OFF_WO   5898240

__device__ __forceinline__ unsigned f2tf(float f) {
    unsigned u;
    asm("cvt.rna.tf32.f32 %0, %1;" : "=r"(u) : "f"(f));
    return u;
}
__device__ __forceinline__ float2 tf2(float a, float b) {
    return make_float2(__uint_as_float(f2tf(a)), __uint_as_float(f2tf(b)));
}
__device__ __forceinline__ void mma_tf32(float* d, const unsigned* a, const unsigned* b) {
    asm volatile(
        "mma.sync.aligned.m16n8k8.row.col.f32.tf32.tf32.f32 "
        "{%0,%1,%2,%3}, {%4,%5,%6,%7}, {%8,%9}, {%0,%1,%2,%3};"
        : "+f"(d[0]), "+f"(d[1]), "+f"(d[2]), "+f"(d[3])
        : "r"(a[0]), "r"(a[1]), "r"(a[2]), "r"(a[3]), "r"(b[0]), "r"(b[1]));
}
__device__ __forceinline__ void cp16(void* dst, const void* src, bool valid) {
    unsigned d = (unsigned)__cvta_generic_to_shared(dst);
    int sz = valid ? 16 : 0;
    asm volatile("cp.async.cg.shared.global [%0], [%1], 16, %2;\n"
                 :: "r"(d), "l"(src), "r"(sz) : "memory");
}

// ---------------------------------------------------------------------------
// Pre-round pass: tf32-round x and all weights into scratch (float4-wide).
// float4 index ranges: x = [0, 2097152); weights flat j = i - 2097152.
// ---------------------------------------------------------------------------
__global__ void __launch_bounds__(256)
preround(const float4* __restrict__ x,
         const float4* __restrict__ wdq, const float4* __restrict__ wdkv,
         const float4* __restrict__ wkr, const float4* __restrict__ wuq,
         const float4* __restrict__ wqr, const float4* __restrict__ wuk,
         const float4* __restrict__ wuv, const float4* __restrict__ wo)
{
    int i = blockIdx.x * blockDim.x + threadIdx.x;
    const float4* s;
    float4* d;
    if (i < 2097152) {
        s = x + i;
        d = (float4*)g_x + i;
    } else {
        int j = i - 2097152;
        if (j >= 2523136) return;
        float4* gw = (float4*)g_w;
        if      (j <  262144) s = wdq  + j;
        else if (j <  524288) s = wdkv + (j -  262144);
        else if (j <  557056) s = wkr  + (j -  524288);
        else if (j <  819200) s = wuq  + (j -  557056);
        else if (j <  950272) s = wqr  + (j -  819200);
        else if (j < 1212416) s = wuk  + (j -  950272);
        else if (j < 1474560) s = wuv  + (j - 1212416);
        else                  s = wo   + (j - 1474560);
        d = gw + j;
    }
    float4 v = *s;
    v.x = __uint_as_float(f2tf(v.x));
    v.y = __uint_as_float(f2tf(v.y));
    v.z = __uint_as_float(f2tf(v.z));
    v.w = __uint_as_float(f2tf(v.w));
    *d = v;
}

// ---------------------------------------------------------------------------
// 4-stage cp.async tf32 GEMM, NT. 256 threads, 8 warps as 4m x 2n,
// warp tile m32 x n64. M fixed = 4096. ALL operands tf32-pre-rounded in
// gmem, so fragment loads are raw LDS (zero CVT in the inner loop).
// B side = up to 3 row-concatenated weight matrices (split nb1/nb2).
// MODE 0: plain Cout ; 5: x-proj split ; 6: cq-proj ; 7: ckv-proj
// ---------------------------------------------------------------------------
#define GEMM_SMEM_BYTES (8 * 2560 * 4)   // 81920

template<int MODE>
__global__ void __launch_bounds__(256, 2)
gemm8(const float* __restrict__ A,
      const float* __restrict__ B0, const float* __restrict__ B1,
      const float* __restrict__ B2, int nb1, int nb2,
      int N, int K, int lda, int ldb,
      float* __restrict__ Cout, int ldc,
      const float* __restrict__ fc, const float* __restrict__ fs)
{
    extern __shared__ float gsm[];
    float* As = gsm;             // 4 stages x 128 x 20
    float* Bs = gsm + 4 * 2560;

    const int m0 = blockIdx.y * 128;
    const int n0 = blockIdx.x * 128;
    const int tid  = threadIdx.x;
    const int wid  = tid >> 5;
    const int lane = tid & 31;
    const int g    = lane >> 2;
    const int tig  = lane & 3;
    const int wr   = (wid & 3) * 32;
    const int wc   = (wid >> 2) * 64;
    const int lrow = tid >> 2;
    const int lkq  = (tid & 3) * 4;
    const int nk   = K / 16;

    float acc[2][8][4];
    #pragma unroll
    for (int i = 0; i < 2; i++)
        #pragma unroll
        for (int j = 0; j < 8; j++)
            #pragma unroll
            for (int r = 0; r < 4; r++) acc[i][j][r] = 0.f;

    auto issue = [&](int kt) {
        int s = kt & 3;
        #pragma unroll
        for (int i = 0; i < 2; i++) {
            int r = lrow + i * 64;
            cp16(As + s * 2560 + r * 20 + lkq,
                 A + (size_t)(m0 + r) * lda + kt * 16 + lkq, true);
            int br = n0 + r;
            const float* bp = (br < nb1) ? B0 + (size_t)br * ldb
                            : (br < nb2) ? B1 + (size_t)(br - nb1) * ldb
                                         : B2 + (size_t)(br - nb2) * ldb;
            cp16(Bs + s * 2560 + r * 20 + lkq, bp + kt * 16 + lkq, br < N);
        }
        asm volatile("cp.async.commit_group;\n" ::: "memory");
    };

    issue(0); issue(1); issue(2);
    asm volatile("cp.async.wait_group 2;\n" ::: "memory");
    __syncthreads();

    for (int kt = 0; kt < nk; kt++) {
        if (kt + 3 < nk) issue(kt + 3);
        else asm volatile("cp.async.commit_group;\n" ::: "memory");

        const float* Ab = As + (kt & 3) * 2560;
        const float* Bb = Bs + (kt & 3) * 2560;
        #pragma unroll
        for (int kk = 0; kk < 2; kk++) {
            unsigned af[2][4], bf[8][2];
            #pragma unroll
            for (int ti = 0; ti < 2; ti++) {
                int r0 = (wr + ti * 16 + g) * 20 + kk * 8 + tig;
                af[ti][0] = __float_as_uint(Ab[r0]);
                af[ti][1] = __float_as_uint(Ab[r0 + 160]);
                af[ti][2] = __float_as_uint(Ab[r0 + 4]);
                af[ti][3] = __float_as_uint(Ab[r0 + 164]);
            }
            #pragma unroll
            for (int tj = 0; tj < 8; tj++) {
                int r0 = (wc + tj * 8 + g) * 20 + kk * 8 + tig;
                bf[tj][0] = __float_as_uint(Bb[r0]);
                bf[tj][1] = __float_as_uint(Bb[r0 + 4]);
            }
            #pragma unroll
            for (int ti = 0; ti < 2; ti++)
                #pragma unroll
                for (int tj = 0; tj < 8; tj++)
                    mma_tf32(acc[ti][tj], af[ti], bf[tj]);
        }
        asm volatile("cp.async.wait_group 2;\n" ::: "memory");
        __syncthreads();
    }

    #pragma unroll
    for (int ti = 0; ti < 2; ti++) {
        #pragma unroll
        for (int rh = 0; rh < 2; rh++) {
            int gm = m0 + wr + ti * 16 + g + rh * 8;
            int bb = gm >> 11;
            int tt = gm & (T_ - 1);
            #pragma unroll
            for (int tj = 0; tj < 8; tj++) {
                int gn = n0 + wc + tj * 8 + tig * 2;
                float v0 = acc[ti][tj][rh * 2 + 0];
                float v1 = acc[ti][tj][rh * 2 + 1];
                if (MODE == 0) {
                    if (gn < N)
                        *(float2*)(Cout + (size_t)gm * ldc + gn) = make_float2(v0, v1);
                } else if (MODE == 5) {
                    if (gn < 512) {
                        *(float2*)(g_cq + (size_t)gm * 512 + gn) = tf2(v0, v1);
                    } else if (gn < 1024) {
                        *(float2*)(g_ckv + (size_t)gm * 512 + gn - 512) = tf2(v0, v1);
                    } else if (gn < 1088) {
                        int j = gn - 1024;
                        int p = j >> 1;
                        float c = fc[tt * 32 + p], s = fs[tt * 32 + p];
                        float2 o2 = tf2(v0 * c - v1 * s, v0 * s + v1 * c);
                        #pragma unroll
                        for (int hh = 0; hh < H_; hh++)
                            *(float2*)(g_k + ((size_t)(bb * H_ + hh) * T_ + tt) * D_ + HS_ + j) = o2;
                    }
                } else if (MODE == 6) {
                    if (gn < 2048) {
                        int hh = gn >> 7, dd = gn & 127;
                        *(float2*)(g_q + ((size_t)(bb * H_ + hh) * T_ + tt) * D_ + dd) =
                            tf2(v0, v1);
                    } else {
                        int j2 = gn - 2048;
                        int hh = j2 >> 6, jj = j2 & 63;
                        int p = jj >> 1;
                        float c = fc[tt * 32 + p], s = fs[tt * 32 + p];
                        *(float2*)(g_q + ((size_t)(bb * H_ + hh) * T_ + tt) * D_ + HS_ + jj) =
                            tf2(v0 * c - v1 * s, v0 * s + v1 * c);
                    }
                } else if (MODE == 7) {
                    if (gn < 2048) {
                        int hh = gn >> 7, dd = gn & 127;
                        *(float2*)(g_k + ((size_t)(bb * H_ + hh) * T_ + tt) * D_ + dd) =
                            tf2(v0, v1);
                    } else {
                        int t2 = gn - 2048;
                        int hh = t2 >> 7, dd = t2 & 127;
                        *(float2*)(g_v + ((size_t)(bb * H_ + hh) * T_ + tt) * HS_ + dd) =
                            tf2(v0, v1);
                    }
                }
            }
        }
    }
}

// ---------------------------------------------------------------------------
// Fused flash attention v4 (unchanged from R8 except: ao written tf32-rounded
// so the out-projection GEMM needs no CVT either).
// ---------------------------------------------------------------------------
#define QP   196
#define KSP  196
#define VSP  132
#define PP   68
#define FLASH_SMEM_WORDS (128*QP + 64*KSP + 64*VSP + 128*PP)   // 54784
#define FLASH_SMEM_BYTES (FLASH_SMEM_WORDS * 4)                // 219136

__global__ void __launch_bounds__(256, 1)
flash_attn(const float* __restrict__ qg, const float* __restrict__ kg,
           const float* __restrict__ vg, float* __restrict__ ao)
{
    extern __shared__ unsigned smu[];
    unsigned* Qs = smu;                    // [row][k]  (tf32 bits)
    unsigned* Ks = Qs + 128 * QP;          // [key][k]
    unsigned* Vs = Ks + 64 * KSP;          // [key][d]
    unsigned* Ps = Vs + 64 * VSP;          // [row][key] tf32

    const int z  = blockIdx.x;
    const int iy = (int)gridDim.y - 1 - blockIdx.y;
    const int q0 = iy * 128;
    const int b = z / H_, h = z % H_;

    const float* Qg = qg + (size_t)z * T_ * D_;
    const float* Kg = kg + (size_t)z * T_ * D_;
    const float* Vg = vg + (size_t)z * T_ * HS_;

    const int tid = threadIdx.x;
    const int wid = tid >> 5, lane = tid & 31;
    const int g = lane >> 2, tig = lane & 3;
    const int qrow0 = q0 + wid * 16 + g;

    auto issueK = [&](int kt) {
        #pragma unroll
        for (int it = 0; it < 12; it++) {
            int idx = tid + it * 256;
            int row = idx / 48, kq = (idx % 48) * 4;
            cp16(Ks + row * KSP + kq, Kg + (size_t)(kt * 64 + row) * D_ + kq, true);
        }
        asm volatile("cp.async.commit_group;\n" ::: "memory");
    };
    auto issueV = [&](int kt) {
        #pragma unroll
        for (int it = 0; it < 8; it++) {
            int idx = tid + it * 256;
            int kp = idx / 32, dq = (idx % 32) * 4;
            cp16(Vs + kp * VSP + dq, Vg + (size_t)(kt * 64 + kp) * HS_ + dq, true);
        }
        asm volatile("cp.async.commit_group;\n" ::: "memory");
    };

    // Prologue: Q + K0 in one group, V0 in the next
    #pragma unroll
    for (int it = 0; it < 24; it++) {
        int idx = tid + it * 256;
        int row = idx / 48, kq = (idx % 48) * 4;
        cp16(Qs + row * QP + kq, Qg + (size_t)(q0 + row) * D_ + kq, true);
    }
    issueK(0);
    issueV(0);

    float m_i[2] = {-1e30f, -1e30f};
    float l_i[2] = {0.f, 0.f};
    float o[16][4];
    #pragma unroll
    for (int j = 0; j < 16; j++)
        #pragma unroll
        for (int r = 0; r < 4; r++) o[j][r] = 0.f;

    const int nkt = 2 * iy + 2;
    const float scale = 0.07216878364870323f;

    for (int kt = 0; kt < nkt; kt++) {
        asm volatile("cp.async.wait_group 1;\n" ::: "memory");  // Q+K ready
        __syncthreads();

        // S = Q K^T : warp m16 x n64, k=192 (raw tf32 bits)
        float s[8][4];
        #pragma unroll
        for (int j = 0; j < 8; j++)
            #pragma unroll
            for (int r = 0; r < 4; r++) s[j][r] = 0.f;

        #pragma unroll
        for (int kk = 0; kk < 24; kk++) {
            unsigned a[4];
            int r0 = (wid * 16 + g) * QP + kk * 8 + tig;
            a[0] = Qs[r0];          a[1] = Qs[r0 + 8 * QP];
            a[2] = Qs[r0 + 4];      a[3] = Qs[r0 + 8 * QP + 4];
            #pragma unroll
            for (int j = 0; j < 8; j++) {
                unsigned bq[2];
                int rb = (j * 8 + g) * KSP + kk * 8 + tig;
                bq[0] = Ks[rb]; bq[1] = Ks[rb + 4];
                mma_tf32(s[j], a, bq);
            }
        }

        // Online softmax
        const bool diag = (kt >= 2 * iy);
        #pragma unroll
        for (int r2 = 0; r2 < 2; r2++) {
            const int row = qrow0 + r2 * 8;
            float mx = -1e30f;
            #pragma unroll
            for (int j = 0; j < 8; j++) {
                #pragma unroll
                for (int c = 0; c < 2; c++) {
                    int r = r2 * 2 + c;
                    float v = s[j][r] * scale;
                    if (diag) {
                        int col = kt * 64 + j * 8 + 2 * tig + c;
                        if (col > row) v = -1e30f;
                    }
                    s[j][r] = v;
                    mx = fmaxf(mx, v);
                }
            }
            mx = fmaxf(mx, __shfl_xor_sync(0xffffffffu, mx, 1));
            mx = fmaxf(mx, __shfl_xor_sync(0xffffffffu, mx, 2));
            float mnew = fmaxf(m_i[r2], mx);
            float alpha = __expf(m_i[r2] - mnew);
            m_i[r2] = mnew;

            float ls = 0.f;
            #pragma unroll
            for (int j = 0; j < 8; j++) {
                #pragma unroll
                for (int c = 0; c < 2; c++) {
                    int r = r2 * 2 + c;
                    float p = __expf(s[j][r] - mnew);
                    s[j][r] = p;
                    ls += p;
                }
            }
            ls += __shfl_xor_sync(0xffffffffu, ls, 1);
            ls += __shfl_xor_sync(0xffffffffu, ls, 2);
            l_i[r2] = l_i[r2] * alpha + ls;

            #pragma unroll
            for (int j = 0; j < 16; j++) {
                o[j][r2 * 2 + 0] *= alpha;
                o[j][r2 * 2 + 1] *= alpha;
            }
        }

        // P -> smem (tf32, per-warp rows)
        {
            int base0 = (wid * 16 + g) * PP;
            int base1 = (wid * 16 + g + 8) * PP;
            #pragma unroll
            for (int j = 0; j < 8; j++) {
                int cc = j * 8 + 2 * tig;
                Ps[base0 + cc    ] = f2tf(s[j][0]);
                Ps[base0 + cc + 1] = f2tf(s[j][1]);
                Ps[base1 + cc    ] = f2tf(s[j][2]);
                Ps[base1 + cc + 1] = f2tf(s[j][3]);
            }
        }
        __syncwarp();

        asm volatile("cp.async.wait_group 0;\n" ::: "memory");  // V ready
        __syncthreads();                                        // + done with K

        if (kt + 1 < nkt) issueK(kt + 1);   // prefetch next K during PV
        else asm volatile("cp.async.commit_group;\n" ::: "memory");

        // O += P V : warp m16 x n128, k=64 ; V key-major, raw tf32 bits
        #pragma unroll
        for (int kk = 0; kk < 8; kk++) {
            unsigned a[4];
            int r0 = (wid * 16 + g) * PP + kk * 8 + tig;
            a[0] = Ps[r0];          a[1] = Ps[r0 + 8 * PP];
            a[2] = Ps[r0 + 4];      a[3] = Ps[r0 + 8 * PP + 4];
            #pragma unroll
            for (int j = 0; j < 16; j++) {
                unsigned bq[2];
                int cb = j * 8 + g;
                bq[0] = Vs[(kk * 8 + tig    ) * VSP + cb];
                bq[1] = Vs[(kk * 8 + tig + 4) * VSP + cb];
                mma_tf32(o[j], a, bq);
            }
        }

        __syncthreads();                    // done reading V
        if (kt + 1 < nkt) issueV(kt + 1);
        else asm volatile("cp.async.commit_group;\n" ::: "memory");
    }

    const float inv0 = 1.f / l_i[0];
    const float inv1 = 1.f / l_i[1];
    #pragma unroll
    for (int j = 0; j < 16; j++) {
        int d = j * 8 + 2 * tig;
        size_t base0 = ((size_t)(b * T_ + qrow0    )) * C_ + h * HS_ + d;
        size_t base1 = ((size_t)(b * T_ + qrow0 + 8)) * C_ + h * HS_ + d;
        *(float2*)(ao + base0) = tf2(o[j][0] * inv0, o[j][1] * inv0);
        *(float2*)(ao + base1) = tf2(o[j][2] * inv1, o[j][3] * inv1);
    }
}

// ---------------------------------------------------------------------------
// Launch
// ---------------------------------------------------------------------------
extern "C" void kernel_launch(void* const* d_in, const int* in_sizes, int n_in,
                              void* d_out, int out_size)
{
    const float* x    = (const float*)d_in[0];
    const float* fc   = (const float*)d_in[1];
    const float* fs   = (const float*)d_in[2];
    const float* Wdq  = (const float*)d_in[3];
    const float* Wuq  = (const float*)d_in[4];
    const float* Wdkv = (const float*)d_in[5];
    const float* Wuk  = (const float*)d_in[6];
    const float* Wuv  = (const float*)d_in[7];
    const float* Wqr  = (const float*)d_in[8];
    const float* Wkr  = (const float*)d_in[9];
    const float* Wo   = (const float*)d_in[10];
    float* out = (float*)d_out;

    float *cq, *ckv, *q, *k, *v, *ao, *gx, *gw;
    cudaGetSymbolAddress((void**)&cq,  g_cq);
    cudaGetSymbolAddress((void**)&ckv, g_ckv);
    cudaGetSymbolAddress((void**)&q,   g_q);
    cudaGetSymbolAddress((void**)&k,   g_k);
    cudaGetSymbolAddress((void**)&v,   g_v);
    cudaGetSymbolAddress((void**)&ao,  g_ao);
    cudaGetSymbolAddress((void**)&gx,  g_x);
    cudaGetSymbolAddress((void**)&gw,  g_w);

    static bool attr_set = false;
    if (!attr_set) {
        cudaFuncSetAttribute(flash_attn, cudaFuncAttributeMaxDynamicSharedMemorySize,
                             FLASH_SMEM_BYTES);
        cudaFuncSetAttribute(gemm8<0>, cudaFuncAttributeMaxDynamicSharedMemorySize,
                             GEMM_SMEM_BYTES);
        cudaFuncSetAttribute(gemm8<5>, cudaFuncAttributeMaxDynamicSharedMemorySize,
                             GEMM_SMEM_BYTES);
        cudaFuncSetAttribute(gemm8<6>, cudaFuncAttributeMaxDynamicSharedMemorySize,
                             GEMM_SMEM_BYTES);
        cudaFuncSetAttribute(gemm8<7>, cudaFuncAttributeMaxDynamicSharedMemorySize,
                             GEMM_SMEM_BYTES);
        attr_set = true;
    }

    dim3 blk(256);

    // Pre-round x + all weights to tf32 (bit-identical math, CVTs hoisted out
    // of all GEMM inner loops). 4620288 float4 slots.
    preround<<<(4620288 + 255) / 256, 256>>>(
        (const float4*)x, (const float4*)Wdq, (const float4*)Wdkv,
        (const float4*)Wkr, (const float4*)Wuq, (const float4*)Wqr,
        (const float4*)Wuk, (const float4*)Wuv, (const float4*)Wo);

    // GEMM A: x -> [c_q | c_kv | rope-bcast k_r], N=1088, K=2048
    gemm8<5><<<dim3(9, 32), blk, GEMM_SMEM_BYTES>>>(
        gx, gw + OFF_WDQ, gw + OFF_WDKV, gw + OFF_WKR,
        512, 1024, 1088, C_, C_, C_, nullptr, 0, fc, fs);

    // GEMM B: c_q -> [q_c | rope q_r], N=3072, K=512
    gemm8<6><<<dim3(24, 32), blk, GEMM_SMEM_BYTES>>>(
        cq, gw + OFF_WUQ, gw + OFF_WQR, gw + OFF_WQR,
        2048, 3072, 3072, NLQ_, NLQ_, NLQ_, nullptr, 0, fc, fs);

    // GEMM C: c_kv -> [k_c | v], N=4096, K=512
    gemm8<7><<<dim3(32, 32), blk, GEMM_SMEM_BYTES>>>(
        ckv, gw + OFF_WUK, gw + OFF_WUV, gw + OFF_WUV,
        2048, 4096, 4096, NLKV_, NLKV_, NLKV_, nullptr, 0, fc, fs);

    // Fused flash attention
    dim3 gfa(B_ * H_, T_ / 128);
    flash_attn<<<gfa, 256, FLASH_SMEM_BYTES>>>(q, k, v, ao);

    // Output projection
    gemm8<0><<<dim3(16, 32), blk, GEMM_SMEM_BYTES>>>(
        ao, gw + OFF_WO, gw + OFF_WO, gw + OFF_WO,
        4096, 8192, 2048, C_, C_, C_, out, C_, fc, fs);
}

// round 12
// speedup vs baseline: 1.0354x; 1.0354x over previous
#include <cuda_runtime.h>
#include <math.h>
#include <stdint.h>

#define B_   2
#define T_   2048
#define C_   2048
#define H_   16
#define HS_  128
#define NLQ_ 512
#define NLKV_ 512
#define RHD_ 64
#define D_   192

__device__ float g_cq [B_*T_*NLQ_];
__device__ float g_ckv[B_*T_*NLKV_];
__device__ float g_q  [B_*H_*T_*D_];
__device__ float g_k  [B_*H_*T_*D_];
__device__ float g_v  [B_*H_*T_*HS_];
__device__ float g_ao [B_*T_*C_];

__device__ __forceinline__ unsigned f2tf(float f) {
    unsigned u;
    asm("cvt.rna.tf32.f32 %0, %1;" : "=r"(u) : "f"(f));
    return u;
}
__device__ __forceinline__ float2 tf2(float a, float b) {
    return make_float2(__uint_as_float(f2tf(a)), __uint_as_float(f2tf(b)));
}
__device__ __forceinline__ void mma_tf32(float* d, const unsigned* a, const unsigned* b) {
    asm volatile(
        "mma.sync.aligned.m16n8k8.row.col.f32.tf32.tf32.f32 "
        "{%0,%1,%2,%3}, {%4,%5,%6,%7}, {%8,%9}, {%0,%1,%2,%3};"
        : "+f"(d[0]), "+f"(d[1]), "+f"(d[2]), "+f"(d[3])
        : "r"(a[0]), "r"(a[1]), "r"(a[2]), "r"(a[3]), "r"(b[0]), "r"(b[1]));
}
__device__ __forceinline__ void cp16(void* dst, const void* src, bool valid) {
    unsigned d = (unsigned)__cvta_generic_to_shared(dst);
    int sz = valid ? 16 : 0;
    asm volatile("cp.async.cg.shared.global [%0], [%1], 16, %2;\n"
                 :: "r"(d), "l"(src), "r"(sz) : "memory");
}

// ---------------------------------------------------------------------------
// 3-stage cp.async tf32 GEMM, NT, BK=32. 256 threads, 8 warps as 4m x 2n,
// warp tile m32 x n64. M fixed = 4096 (gm = b*T+t).
// A side: two candidate matrices, selected block-uniformly by n0 < aSplit.
// B side: up to 4 row-concatenated weight matrices (splits nb1/nb2/nb3).
// MODE 0: plain Cout[gm*ldc+gn]
// MODE 5: x-proj:   gn<512 cq | <1024 ckv | <1088 rope-bcast k_r
// MODE 8: up-proj:  gn<2048 q | <3072 rope q_r | <5120 k | else v
// ---------------------------------------------------------------------------
#define KP32 36                              // padded stride (words) for BK=32
#define STG_WORDS (2 * 128 * KP32)           // 9216 words per stage (A+B)
#define GEMM_SMEM_BYTES (3 * STG_WORDS * 4)  // 110592

template<int MODE>
__global__ void __launch_bounds__(256, 2)
gemm32(const float* __restrict__ A0, const float* __restrict__ A1, int aSplit,
       const float* __restrict__ B0, const float* __restrict__ B1,
       const float* __restrict__ B2, const float* __restrict__ B3,
       int nb1, int nb2, int nb3,
       int N, int K, int lda, int ldb,
       float* __restrict__ Cout, int ldc,
       const float* __restrict__ fc, const float* __restrict__ fs)
{
    extern __shared__ float gsm[];

    const int m0 = blockIdx.y * 128;
    const int n0 = blockIdx.x * 128;
    const float* A = (n0 < aSplit) ? A0 : A1;

    const int tid  = threadIdx.x;
    const int wid  = tid >> 5;
    const int lane = tid & 31;
    const int g    = lane >> 2;
    const int tig  = lane & 3;
    const int wr   = (wid & 3) * 32;
    const int wc   = (wid >> 2) * 64;
    const int lrow = tid >> 3;          // 0..31
    const int lkq  = (tid & 7) * 4;     // 0..28
    const int nk   = K / 32;

    float acc[2][8][4];
    #pragma unroll
    for (int i = 0; i < 2; i++)
        #pragma unroll
        for (int j = 0; j < 8; j++)
            #pragma unroll
            for (int r = 0; r < 4; r++) acc[i][j][r] = 0.f;

    auto issue = [&](int kt) {
        float* SA = gsm + (kt % 3) * STG_WORDS;
        float* SB = SA + 128 * KP32;
        #pragma unroll
        for (int i = 0; i < 4; i++) {
            int r = lrow + i * 32;
            cp16(SA + r * KP32 + lkq,
                 A + (size_t)(m0 + r) * lda + kt * 32 + lkq, true);
            int br = n0 + r;
            const float* bp = (br < nb1) ? B0 + (size_t)br * ldb
                            : (br < nb2) ? B1 + (size_t)(br - nb1) * ldb
                            : (br < nb3) ? B2 + (size_t)(br - nb2) * ldb
                                         : B3 + (size_t)(br - nb3) * ldb;
            cp16(SB + r * KP32 + lkq, bp + kt * 32 + lkq, br < N);
        }
        asm volatile("cp.async.commit_group;\n" ::: "memory");
    };

    issue(0); issue(1);
    asm volatile("cp.async.wait_group 1;\n" ::: "memory");
    __syncthreads();

    for (int kt = 0; kt < nk; kt++) {
        if (kt + 2 < nk) issue(kt + 2);
        else asm volatile("cp.async.commit_group;\n" ::: "memory");

        const float* Ab = gsm + (kt % 3) * STG_WORDS;
        const float* Bb = Ab + 128 * KP32;
        #pragma unroll
        for (int kk = 0; kk < 4; kk++) {
            unsigned af[2][4], bf[8][2];
            #pragma unroll
            for (int ti = 0; ti < 2; ti++) {
                int r0 = (wr + ti * 16 + g) * KP32 + kk * 8 + tig;
                af[ti][0] = f2tf(Ab[r0]);
                af[ti][1] = f2tf(Ab[r0 + 8 * KP32]);
                af[ti][2] = f2tf(Ab[r0 + 4]);
                af[ti][3] = f2tf(Ab[r0 + 8 * KP32 + 4]);
            }
            #pragma unroll
            for (int tj = 0; tj < 8; tj++) {
                int r0 = (wc + tj * 8 + g) * KP32 + kk * 8 + tig;
                bf[tj][0] = f2tf(Bb[r0]);
                bf[tj][1] = f2tf(Bb[r0 + 4]);
            }
            #pragma unroll
            for (int ti = 0; ti < 2; ti++)
                #pragma unroll
                for (int tj = 0; tj < 8; tj++)
                    mma_tf32(acc[ti][tj], af[ti], bf[tj]);
        }
        asm volatile("cp.async.wait_group 1;\n" ::: "memory");
        __syncthreads();
    }

    #pragma unroll
    for (int ti = 0; ti < 2; ti++) {
        #pragma unroll
        for (int rh = 0; rh < 2; rh++) {
            int gm = m0 + wr + ti * 16 + g + rh * 8;
            int bb = gm >> 11;
            int tt = gm & (T_ - 1);
            #pragma unroll
            for (int tj = 0; tj < 8; tj++) {
                int gn = n0 + wc + tj * 8 + tig * 2;
                float v0 = acc[ti][tj][rh * 2 + 0];
                float v1 = acc[ti][tj][rh * 2 + 1];
                if (MODE == 0) {
                    if (gn < N)
                        *(float2*)(Cout + (size_t)gm * ldc + gn) = make_float2(v0, v1);
                } else if (MODE == 5) {
                    if (gn < 512) {
                        *(float2*)(g_cq + (size_t)gm * 512 + gn) = make_float2(v0, v1);
                    } else if (gn < 1024) {
                        *(float2*)(g_ckv + (size_t)gm * 512 + gn - 512) = make_float2(v0, v1);
                    } else if (gn < 1088) {
                        int j = gn - 1024;
                        int p = j >> 1;
                        float c = fc[tt * 32 + p], s = fs[tt * 32 + p];
                        float2 o2 = tf2(v0 * c - v1 * s, v0 * s + v1 * c);
                        #pragma unroll
                        for (int hh = 0; hh < H_; hh++)
                            *(float2*)(g_k + ((size_t)(bb * H_ + hh) * T_ + tt) * D_ + HS_ + j) = o2;
                    }
                } else if (MODE == 8) {
                    if (gn < 2048) {
                        int hh = gn >> 7, dd = gn & 127;
                        *(float2*)(g_q + ((size_t)(bb * H_ + hh) * T_ + tt) * D_ + dd) =
                            tf2(v0, v1);
                    } else if (gn < 3072) {
                        int j2 = gn - 2048;
                        int hh = j2 >> 6, jj = j2 & 63;
                        int p = jj >> 1;
                        float c = fc[tt * 32 + p], s = fs[tt * 32 + p];
                        *(float2*)(g_q + ((size_t)(bb * H_ + hh) * T_ + tt) * D_ + HS_ + jj) =
                            tf2(v0 * c - v1 * s, v0 * s + v1 * c);
                    } else if (gn < 5120) {
                        int t2 = gn - 3072;
                        int hh = t2 >> 7, dd = t2 & 127;
                        *(float2*)(g_k + ((size_t)(bb * H_ + hh) * T_ + tt) * D_ + dd) =
                            tf2(v0, v1);
                    } else {
                        int t3 = gn - 5120;
                        int hh = t3 >> 7, dd = t3 & 127;
                        *(float2*)(g_v + ((size_t)(bb * H_ + hh) * T_ + tt) * HS_ + dd) =
                            tf2(v0, v1);
                    }
                }
            }
        }
    }
}

// ---------------------------------------------------------------------------
// Fused flash attention v4 (R8/R9 version, unchanged — proven 372us).
// ---------------------------------------------------------------------------
#define QP   196
#define KSP  196
#define VSP  132
#define PP   68
#define FLASH_SMEM_WORDS (128*QP + 64*KSP + 64*VSP + 128*PP)
#define FLASH_SMEM_BYTES (FLASH_SMEM_WORDS * 4)

__global__ void __launch_bounds__(256, 1)
flash_attn(const float* __restrict__ qg, const float* __restrict__ kg,
           const float* __restrict__ vg, float* __restrict__ ao)
{
    extern __shared__ unsigned smu[];
    unsigned* Qs = smu;
    unsigned* Ks = Qs + 128 * QP;
    unsigned* Vs = Ks + 64 * KSP;
    unsigned* Ps = Vs + 64 * VSP;

    const int z  = blockIdx.x;
    const int iy = (int)gridDim.y - 1 - blockIdx.y;
    const int q0 = iy * 128;
    const int b = z / H_, h = z % H_;

    const float* Qg = qg + (size_t)z * T_ * D_;
    const float* Kg = kg + (size_t)z * T_ * D_;
    const float* Vg = vg + (size_t)z * T_ * HS_;

    const int tid = threadIdx.x;
    const int wid = tid >> 5, lane = tid & 31;
    const int g = lane >> 2, tig = lane & 3;
    const int qrow0 = q0 + wid * 16 + g;

    auto issueK = [&](int kt) {
        #pragma unroll
        for (int it = 0; it < 12; it++) {
            int idx = tid + it * 256;
            int row = idx / 48, kq = (idx % 48) * 4;
            cp16(Ks + row * KSP + kq, Kg + (size_t)(kt * 64 + row) * D_ + kq, true);
        }
        asm volatile("cp.async.commit_group;\n" ::: "memory");
    };
    auto issueV = [&](int kt) {
        #pragma unroll
        for (int it = 0; it < 8; it++) {
            int idx = tid + it * 256;
            int kp = idx / 32, dq = (idx % 32) * 4;
            cp16(Vs + kp * VSP + dq, Vg + (size_t)(kt * 64 + kp) * HS_ + dq, true);
        }
        asm volatile("cp.async.commit_group;\n" ::: "memory");
    };

    #pragma unroll
    for (int it = 0; it < 24; it++) {
        int idx = tid + it * 256;
        int row = idx / 48, kq = (idx % 48) * 4;
        cp16(Qs + row * QP + kq, Qg + (size_t)(q0 + row) * D_ + kq, true);
    }
    issueK(0);
    issueV(0);

    float m_i[2] = {-1e30f, -1e30f};
    float l_i[2] = {0.f, 0.f};
    float o[16][4];
    #pragma unroll
    for (int j = 0; j < 16; j++)
        #pragma unroll
        for (int r = 0; r < 4; r++) o[j][r] = 0.f;

    const int nkt = 2 * iy + 2;
    const float scale = 0.07216878364870323f;

    for (int kt = 0; kt < nkt; kt++) {
        asm volatile("cp.async.wait_group 1;\n" ::: "memory");
        __syncthreads();

        float s[8][4];
        #pragma unroll
        for (int j = 0; j < 8; j++)
            #pragma unroll
            for (int r = 0; r < 4; r++) s[j][r] = 0.f;

        #pragma unroll
        for (int kk = 0; kk < 24; kk++) {
            unsigned a[4];
            int r0 = (wid * 16 + g) * QP + kk * 8 + tig;
            a[0] = Qs[r0];          a[1] = Qs[r0 + 8 * QP];
            a[2] = Qs[r0 + 4];      a[3] = Qs[r0 + 8 * QP + 4];
            #pragma unroll
            for (int j = 0; j < 8; j++) {
                unsigned bq[2];
                int rb = (j * 8 + g) * KSP + kk * 8 + tig;
                bq[0] = Ks[rb]; bq[1] = Ks[rb + 4];
                mma_tf32(s[j], a, bq);
            }
        }

        const bool diag = (kt >= 2 * iy);
        #pragma unroll
        for (int r2 = 0; r2 < 2; r2++) {
            const int row = qrow0 + r2 * 8;
            float mx = -1e30f;
            #pragma unroll
            for (int j = 0; j < 8; j++) {
                #pragma unroll
                for (int c = 0; c < 2; c++) {
                    int r = r2 * 2 + c;
                    float v = s[j][r] * scale;
                    if (diag) {
                        int col = kt * 64 + j * 8 + 2 * tig + c;
                        if (col > row) v = -1e30f;
                    }
                    s[j][r] = v;
                    mx = fmaxf(mx, v);
                }
            }
            mx = fmaxf(mx, __shfl_xor_sync(0xffffffffu, mx, 1));
            mx = fmaxf(mx, __shfl_xor_sync(0xffffffffu, mx, 2));
            float mnew = fmaxf(m_i[r2], mx);
            float alpha = __expf(m_i[r2] - mnew);
            m_i[r2] = mnew;

            float ls = 0.f;
            #pragma unroll
            for (int j = 0; j < 8; j++) {
                #pragma unroll
                for (int c = 0; c < 2; c++) {
                    int r = r2 * 2 + c;
                    float p = __expf(s[j][r] - mnew);
                    s[j][r] = p;
                    ls += p;
                }
            }
            ls += __shfl_xor_sync(0xffffffffu, ls, 1);
            ls += __shfl_xor_sync(0xffffffffu, ls, 2);
            l_i[r2] = l_i[r2] * alpha + ls;

            #pragma unroll
            for (int j = 0; j < 16; j++) {
                o[j][r2 * 2 + 0] *= alpha;
                o[j][r2 * 2 + 1] *= alpha;
            }
        }

        {
            int base0 = (wid * 16 + g) * PP;
            int base1 = (wid * 16 + g + 8) * PP;
            #pragma unroll
            for (int j = 0; j < 8; j++) {
                int cc = j * 8 + 2 * tig;
                Ps[base0 + cc    ] = f2tf(s[j][0]);
                Ps[base0 + cc + 1] = f2tf(s[j][1]);
                Ps[base1 + cc    ] = f2tf(s[j][2]);
                Ps[base1 + cc + 1] = f2tf(s[j][3]);
            }
        }
        __syncwarp();

        asm volatile("cp.async.wait_group 0;\n" ::: "memory");
        __syncthreads();

        if (kt + 1 < nkt) issueK(kt + 1);
        else asm volatile("cp.async.commit_group;\n" ::: "memory");

        #pragma unroll
        for (int kk = 0; kk < 8; kk++) {
            unsigned a[4];
            int r0 = (wid * 16 + g) * PP + kk * 8 + tig;
            a[0] = Ps[r0];          a[1] = Ps[r0 + 8 * PP];
            a[2] = Ps[r0 + 4];      a[3] = Ps[r0 + 8 * PP + 4];
            #pragma unroll
            for (int j = 0; j < 16; j++) {
                unsigned bq[2];
                int cb = j * 8 + g;
                bq[0] = Vs[(kk * 8 + tig    ) * VSP + cb];
                bq[1] = Vs[(kk * 8 + tig + 4) * VSP + cb];
                mma_tf32(o[j], a, bq);
            }
        }

        __syncthreads();
        if (kt + 1 < nkt) issueV(kt + 1);
        else asm volatile("cp.async.commit_group;\n" ::: "memory");
    }

    const float inv0 = 1.f / l_i[0];
    const float inv1 = 1.f / l_i[1];
    #pragma unroll
    for (int j = 0; j < 16; j++) {
        int d = j * 8 + 2 * tig;
        size_t base0 = ((size_t)(b * T_ + qrow0    )) * C_ + h * HS_ + d;
        size_t base1 = ((size_t)(b * T_ + qrow0 + 8)) * C_ + h * HS_ + d;
        *(float2*)(ao + base0) = tf2(o[j][0] * inv0, o[j][1] * inv0);
        *(float2*)(ao + base1) = tf2(o[j][2] * inv1, o[j][3] * inv1);
    }
}

// ---------------------------------------------------------------------------
// Launch
// ---------------------------------------------------------------------------
extern "C" void kernel_launch(void* const* d_in, const int* in_sizes, int n_in,
                              void* d_out, int out_size)
{
    const float* x    = (const float*)d_in[0];
    const float* fc   = (const float*)d_in[1];
    const float* fs   = (const float*)d_in[2];
    const float* Wdq  = (const float*)d_in[3];
    const float* Wuq  = (const float*)d_in[4];
    const float* Wdkv = (const float*)d_in[5];
    const float* Wuk  = (const float*)d_in[6];
    const float* Wuv  = (const float*)d_in[7];
    const float* Wqr  = (const float*)d_in[8];
    const float* Wkr  = (const float*)d_in[9];
    const float* Wo   = (const float*)d_in[10];
    float* out = (float*)d_out;

    float *cq, *ckv, *q, *k, *v, *ao;
    cudaGetSymbolAddress((void**)&cq,  g_cq);
    cudaGetSymbolAddress((void**)&ckv, g_ckv);
    cudaGetSymbolAddress((void**)&q,   g_q);
    cudaGetSymbolAddress((void**)&k,   g_k);
    cudaGetSymbolAddress((void**)&v,   g_v);
    cudaGetSymbolAddress((void**)&ao,  g_ao);

    static bool attr_set = false;
    if (!attr_set) {
        cudaFuncSetAttribute(flash_attn, cudaFuncAttributeMaxDynamicSharedMemorySize,
                             FLASH_SMEM_BYTES);
        cudaFuncSetAttribute(gemm32<0>, cudaFuncAttributeMaxDynamicSharedMemorySize,
                             GEMM_SMEM_BYTES);
        cudaFuncSetAttribute(gemm32<5>, cudaFuncAttributeMaxDynamicSharedMemorySize,
                             GEMM_SMEM_BYTES);
        cudaFuncSetAttribute(gemm32<8>, cudaFuncAttributeMaxDynamicSharedMemorySize,
                             GEMM_SMEM_BYTES);
        attr_set = true;
    }

    dim3 blk(256);
    const int HUGE = 1 << 29;

    // GEMM A: x -> [c_q | c_kv | rope-bcast k_r], N=1088, K=2048
    gemm32<5><<<dim3(9, 32), blk, GEMM_SMEM_BYTES>>>(
        x, x, HUGE,
        Wdq, Wdkv, Wkr, Wkr, 512, 1024, 1088,
        1088, C_, C_, C_, nullptr, 0, fc, fs);

    // GEMM B+C merged: [cq | ckv] -> [q_c | rope q_r | k_c | v], N=7168, K=512
    gemm32<8><<<dim3(56, 32), blk, GEMM_SMEM_BYTES>>>(
        cq, ckv, 3072,
        Wuq, Wqr, Wuk, Wuv, 2048, 3072, 5120,
        7168, NLQ_, NLQ_, NLQ_, nullptr, 0, fc, fs);

    // Fused flash attention
    dim3 gfa(B_ * H_, T_ / 128);
    flash_attn<<<gfa, 256, FLASH_SMEM_BYTES>>>(q, k, v, ao);

    // Output projection
    gemm32<0><<<dim3(16, 32), blk, GEMM_SMEM_BYTES>>>(
        ao, ao, HUGE,
        Wo, Wo, Wo, Wo, HUGE, HUGE, HUGE,
        2048, C_, C_, C_, out, C_, fc, fs);
}

// round 14
// speedup vs baseline: 1.9458x; 1.8793x over previous
#include <cuda_runtime.h>
#include <cuda_fp16.h>
#include <math.h>
#include <stdint.h>

#define B_   2
#define T_   2048
#define C_   2048
#define H_   16
#define HS_  128
#define NLQ_ 512
#define NLKV_ 512
#define RHD_ 64
#define D_   192

// Scratch (all operands fp16)
__device__ __half g_xh[B_*T_*C_];
__device__ __half g_wh[10092544];
__device__ __half g_cq [B_*T_*NLQ_];
__device__ __half g_ckv[B_*T_*NLKV_];
__device__ __half g_q  [B_*H_*T_*D_];     // (b,h,t,192)
__device__ __half g_k  [B_*H_*T_*D_];     // (b,h,t,192)
__device__ __half g_v  [B_*H_*HS_*T_];    // (b,h,d,t)  <- d-major for PV fragments
__device__ __half g_ao [B_*T_*C_];        // (b,t,h*hs)

// half offsets into g_wh
#define OFF_WDQ  0
#define OFF_WDKV 1048576
#define OFF_WKR  2097152
#define OFF_WUQ  2228224
#define OFF_WQR  3276800
#define OFF_WUK  3801088
#define OFF_WUV  4849664
#define OFF_WO   5898240

__device__ __forceinline__ void mma_f16(float* d, const unsigned* a, const unsigned* b) {
    asm volatile(
        "mma.sync.aligned.m16n8k16.row.col.f32.f16.f16.f32 "
        "{%0,%1,%2,%3}, {%4,%5,%6,%7}, {%8,%9}, {%0,%1,%2,%3};"
        : "+f"(d[0]), "+f"(d[1]), "+f"(d[2]), "+f"(d[3])
        : "r"(a[0]), "r"(a[1]), "r"(a[2]), "r"(a[3]), "r"(b[0]), "r"(b[1]));
}
__device__ __forceinline__ void cp16(void* dst, const void* src, bool valid) {
    unsigned d = (unsigned)__cvta_generic_to_shared(dst);
    int sz = valid ? 16 : 0;
    asm volatile("cp.async.cg.shared.global [%0], [%1], 16, %2;\n"
                 :: "r"(d), "l"(src), "r"(sz) : "memory");
}
__device__ __forceinline__ unsigned packh2(float a, float b) {
    __half2 h = __floats2half2_rn(a, b);
    return *(unsigned*)&h;
}
__device__ __forceinline__ void st_h2(__half* p, float a, float b) {
    *(__half2*)p = __floats2half2_rn(a, b);
}

// ---------------------------------------------------------------------------
// Pre-convert pass: fp32 x + all weights -> fp16 scratch (float4 -> 4 halfs).
// ---------------------------------------------------------------------------
__global__ void __launch_bounds__(256)
preconv(const float4* __restrict__ x,
        const float4* __restrict__ wdq, const float4* __restrict__ wdkv,
        const float4* __restrict__ wkr, const float4* __restrict__ wuq,
        const float4* __restrict__ wqr, const float4* __restrict__ wuk,
        const float4* __restrict__ wuv, const float4* __restrict__ wo)
{
    int i = blockIdx.x * blockDim.x + threadIdx.x;
    const float4* s;
    __half* d;
    if (i < 2097152) {
        s = x + i;
        d = g_xh + (size_t)i * 4;
    } else {
        int j = i - 2097152;
        if (j >= 2523136) return;
        if      (j <  262144) s = wdq  + j;
        else if (j <  524288) s = wdkv + (j -  262144);
        else if (j <  557056) s = wkr  + (j -  524288);
        else if (j <  819200) s = wuq  + (j -  557056);
        else if (j <  950272) s = wqr  + (j -  819200);
        else if (j < 1212416) s = wuk  + (j -  950272);
        else if (j < 1474560) s = wuv  + (j - 1212416);
        else                  s = wo   + (j - 1474560);
        d = g_wh + (size_t)j * 4;
    }
    float4 v = *s;
    __half2 lo = __floats2half2_rn(v.x, v.y);
    __half2 hi = __floats2half2_rn(v.z, v.w);
    *(uint2*)d = make_uint2(*(unsigned*)&lo, *(unsigned*)&hi);
}

// ---------------------------------------------------------------------------
// 3-stage cp.async fp16 GEMM (m16n8k16), NT. 256 thr, 8 warps 4m x 2n,
// warp tile m32 x n64, K-tile = 64 halfs (32 words). M fixed = 4096.
// A: two candidates selected by n0 < aSplit. B: 4-way row concat.
// MODE 0: float Cout ; MODE 5: x-proj split ; MODE 8: merged up-proj.
// ---------------------------------------------------------------------------
#define KPW 36
#define STGW (2 * 128 * KPW)                 // 9216 words / stage
#define GEMM_SMEM_BYTES (3 * STGW * 4)       // 110592

template<int MODE>
__global__ void __launch_bounds__(256, 2)
gemmh(const __half* __restrict__ A0, const __half* __restrict__ A1, int aSplit,
      const __half* __restrict__ B0, const __half* __restrict__ B1,
      const __half* __restrict__ B2, const __half* __restrict__ B3,
      int nb1, int nb2, int nb3,
      int N, int K, int lda, int ldb,
      float* __restrict__ Cout, int ldc,
      const float* __restrict__ fc, const float* __restrict__ fs)
{
    extern __shared__ unsigned gsm[];

    const int m0 = blockIdx.y * 128;
    const int n0 = blockIdx.x * 128;
    const __half* A = (n0 < aSplit) ? A0 : A1;

    const int tid  = threadIdx.x;
    const int wid  = tid >> 5;
    const int lane = tid & 31;
    const int g    = lane >> 2;
    const int tig  = lane & 3;
    const int wr   = (wid & 3) * 32;
    const int wc   = (wid >> 2) * 64;
    const int lrow = tid >> 3;          // 0..31
    const int lkh  = (tid & 7) * 8;     // half offset 0..56
    const int nk   = K / 64;

    float acc[2][8][4];
    #pragma unroll
    for (int i = 0; i < 2; i++)
        #pragma unroll
        for (int j = 0; j < 8; j++)
            #pragma unroll
            for (int r = 0; r < 4; r++) acc[i][j][r] = 0.f;

    auto issue = [&](int kt) {
        unsigned* SA = gsm + (kt % 3) * STGW;
        unsigned* SB = SA + 128 * KPW;
        #pragma unroll
        for (int i = 0; i < 4; i++) {
            int r = lrow + i * 32;
            cp16(SA + r * KPW + (lkh >> 1),
                 A + (size_t)(m0 + r) * lda + kt * 64 + lkh, true);
            int br = n0 + r;
            const __half* bp = (br < nb1) ? B0 + (size_t)br * ldb
                             : (br < nb2) ? B1 + (size_t)(br - nb1) * ldb
                             : (br < nb3) ? B2 + (size_t)(br - nb2) * ldb
                                          : B3 + (size_t)(br - nb3) * ldb;
            cp16(SB + r * KPW + (lkh >> 1), bp + kt * 64 + lkh, br < N);
        }
        asm volatile("cp.async.commit_group;\n" ::: "memory");
    };

    issue(0); issue(1);
    asm volatile("cp.async.wait_group 1;\n" ::: "memory");
    __syncthreads();

    for (int kt = 0; kt < nk; kt++) {
        if (kt + 2 < nk) issue(kt + 2);
        else asm volatile("cp.async.commit_group;\n" ::: "memory");

        const unsigned* Ab = gsm + (kt % 3) * STGW;
        const unsigned* Bb = Ab + 128 * KPW;
        #pragma unroll
        for (int kk = 0; kk < 4; kk++) {
            unsigned af[2][4], bf[8][2];
            #pragma unroll
            for (int ti = 0; ti < 2; ti++) {
                int r0 = (wr + ti * 16 + g) * KPW + kk * 8 + tig;
                af[ti][0] = Ab[r0];
                af[ti][1] = Ab[r0 + 8 * KPW];
                af[ti][2] = Ab[r0 + 4];
                af[ti][3] = Ab[r0 + 8 * KPW + 4];
            }
            #pragma unroll
            for (int tj = 0; tj < 8; tj++) {
                int r0 = (wc + tj * 8 + g) * KPW + kk * 8 + tig;
                bf[tj][0] = Bb[r0];
                bf[tj][1] = Bb[r0 + 4];
            }
            #pragma unroll
            for (int ti = 0; ti < 2; ti++)
                #pragma unroll
                for (int tj = 0; tj < 8; tj++)
                    mma_f16(acc[ti][tj], af[ti], bf[tj]);
        }
        asm volatile("cp.async.wait_group 1;\n" ::: "memory");
        __syncthreads();
    }

    #pragma unroll
    for (int ti = 0; ti < 2; ti++) {
        #pragma unroll
        for (int rh = 0; rh < 2; rh++) {
            int gm = m0 + wr + ti * 16 + g + rh * 8;
            int bb = gm >> 11;
            int tt = gm & (T_ - 1);
            #pragma unroll
            for (int tj = 0; tj < 8; tj++) {
                int gn = n0 + wc + tj * 8 + tig * 2;
                float v0 = acc[ti][tj][rh * 2 + 0];
                float v1 = acc[ti][tj][rh * 2 + 1];
                if (MODE == 0) {
                    if (gn < N)
                        *(float2*)(Cout + (size_t)gm * ldc + gn) = make_float2(v0, v1);
                } else if (MODE == 5) {
                    if (gn < 512) {
                        st_h2(g_cq + (size_t)gm * 512 + gn, v0, v1);
                    } else if (gn < 1024) {
                        st_h2(g_ckv + (size_t)gm * 512 + gn - 512, v0, v1);
                    } else if (gn < 1088) {
                        int j = gn - 1024;
                        int p = j >> 1;
                        float c = fc[tt * 32 + p], s = fs[tt * 32 + p];
                        float o0 = v0 * c - v1 * s;
                        float o1 = v0 * s + v1 * c;
                        #pragma unroll
                        for (int hh = 0; hh < H_; hh++)
                            st_h2(g_k + ((size_t)(bb * H_ + hh) * T_ + tt) * D_ + HS_ + j, o0, o1);
                    }
                } else if (MODE == 8) {
                    if (gn < 2048) {
                        int hh = gn >> 7, dd = gn & 127;
                        st_h2(g_q + ((size_t)(bb * H_ + hh) * T_ + tt) * D_ + dd, v0, v1);
                    } else if (gn < 3072) {
                        int j2 = gn - 2048;
                        int hh = j2 >> 6, jj = j2 & 63;
                        int p = jj >> 1;
                        float c = fc[tt * 32 + p], s = fs[tt * 32 + p];
                        st_h2(g_q + ((size_t)(bb * H_ + hh) * T_ + tt) * D_ + HS_ + jj,
                              v0 * c - v1 * s, v0 * s + v1 * c);
                    } else if (gn < 5120) {
                        int t2 = gn - 3072;
                        int hh = t2 >> 7, dd = t2 & 127;
                        st_h2(g_k + ((size_t)(bb * H_ + hh) * T_ + tt) * D_ + dd, v0, v1);
                    } else {
                        int t3 = gn - 5120;
                        int hh = t3 >> 7, dd = t3 & 127;
                        __half* vp = g_v + ((size_t)(bb * H_ + hh) * HS_ + dd) * T_ + tt;
                        vp[0]  = __float2half(v0);
                        vp[T_] = __float2half(v1);
                    }
                }
            }
        }
    }
}

// ---------------------------------------------------------------------------
// Fused flash attention, fp16 operands (m16n8k16), fp32 softmax/accum.
// Q [128][100w], K [64][100w], V d-major [128][36w], P [128][36w].
// cp.async split-wait pipeline identical to the proven v4 structure.
// ---------------------------------------------------------------------------
#define QPW  100
#define KPW2 100
#define VPW  36
#define PPW  36
#define FLASH_SMEM_WORDS (128*QPW + 64*KPW2 + 128*VPW + 128*PPW)  // 28416
#define FLASH_SMEM_BYTES (FLASH_SMEM_WORDS * 4)                   // 113664

__global__ void __launch_bounds__(256, 1)
flash_attn(const __half* __restrict__ qg, const __half* __restrict__ kg,
           const __half* __restrict__ vg, __half* __restrict__ ao)
{
    extern __shared__ unsigned smu[];
    unsigned* Qs = smu;
    unsigned* Ks = Qs + 128 * QPW;
    unsigned* Vs = Ks + 64 * KPW2;
    unsigned* Ps = Vs + 128 * VPW;

    const int z  = blockIdx.x;
    const int iy = (int)gridDim.y - 1 - blockIdx.y;
    const int q0 = iy * 128;
    const int b = z / H_, h = z % H_;

    const __half* Qg = qg + (size_t)z * T_ * D_;
    const __half* Kg = kg + (size_t)z * T_ * D_;
    const __half* Vg = vg + (size_t)z * HS_ * T_;   // (d, t)

    const int tid = threadIdx.x;
    const int wid = tid >> 5, lane = tid & 31;
    const int g = lane >> 2, tig = lane & 3;
    const int qrow0 = q0 + wid * 16 + g;

    auto issueK = [&](int kt) {
        #pragma unroll
        for (int it = 0; it < 6; it++) {
            int idx = tid + it * 256;
            int row = idx / 24, kh = (idx % 24) * 8;
            cp16(Ks + row * KPW2 + (kh >> 1),
                 Kg + (size_t)(kt * 64 + row) * D_ + kh, true);
        }
        asm volatile("cp.async.commit_group;\n" ::: "memory");
    };
    auto issueV = [&](int kt) {
        #pragma unroll
        for (int it = 0; it < 4; it++) {
            int idx = tid + it * 256;
            int dd = idx / 8, kh = (idx % 8) * 8;
            cp16(Vs + dd * VPW + (kh >> 1),
                 Vg + (size_t)dd * T_ + kt * 64 + kh, true);
        }
        asm volatile("cp.async.commit_group;\n" ::: "memory");
    };

    // Prologue: Q + K0 one group, V0 next
    #pragma unroll
    for (int it = 0; it < 12; it++) {
        int idx = tid + it * 256;
        int row = idx / 24, kh = (idx % 24) * 8;
        cp16(Qs + row * QPW + (kh >> 1),
             Qg + (size_t)(q0 + row) * D_ + kh, true);
    }
    issueK(0);
    issueV(0);

    float m_i[2] = {-1e30f, -1e30f};
    float l_i[2] = {0.f, 0.f};
    float o[16][4];
    #pragma unroll
    for (int j = 0; j < 16; j++)
        #pragma unroll
        for (int r = 0; r < 4; r++) o[j][r] = 0.f;

    const int nkt = 2 * iy + 2;
    const float scale = 0.07216878364870323f;

    for (int kt = 0; kt < nkt; kt++) {
        asm volatile("cp.async.wait_group 1;\n" ::: "memory");  // Q+K ready
        __syncthreads();

        // S = Q K^T : m16 x n64, k=192 (12 x k16)
        float s[8][4];
        #pragma unroll
        for (int j = 0; j < 8; j++)
            #pragma unroll
            for (int r = 0; r < 4; r++) s[j][r] = 0.f;

        #pragma unroll
        for (int kk = 0; kk < 12; kk++) {
            unsigned a[4];
            int r0 = (wid * 16 + g) * QPW + kk * 8 + tig;
            a[0] = Qs[r0];          a[1] = Qs[r0 + 8 * QPW];
            a[2] = Qs[r0 + 4];      a[3] = Qs[r0 + 8 * QPW + 4];
            #pragma unroll
            for (int j = 0; j < 8; j++) {
                unsigned bq[2];
                int rb = (j * 8 + g) * KPW2 + kk * 8 + tig;
                bq[0] = Ks[rb]; bq[1] = Ks[rb + 4];
                mma_f16(s[j], a, bq);
            }
        }

        // Online softmax (fp32)
        const bool diag = (kt >= 2 * iy);
        #pragma unroll
        for (int r2 = 0; r2 < 2; r2++) {
            const int row = qrow0 + r2 * 8;
            float mx = -1e30f;
            #pragma unroll
            for (int j = 0; j < 8; j++) {
                #pragma unroll
                for (int c = 0; c < 2; c++) {
                    int r = r2 * 2 + c;
                    float v = s[j][r] * scale;
                    if (diag) {
                        int col = kt * 64 + j * 8 + 2 * tig + c;
                        if (col > row) v = -1e30f;
                    }
                    s[j][r] = v;
                    mx = fmaxf(mx, v);
                }
            }
            mx = fmaxf(mx, __shfl_xor_sync(0xffffffffu, mx, 1));
            mx = fmaxf(mx, __shfl_xor_sync(0xffffffffu, mx, 2));
            float mnew = fmaxf(m_i[r2], mx);
            float alpha = __expf(m_i[r2] - mnew);
            m_i[r2] = mnew;

            float ls = 0.f;
            #pragma unroll
            for (int j = 0; j < 8; j++) {
                #pragma unroll
                for (int c = 0; c < 2; c++) {
                    int r = r2 * 2 + c;
                    float p = __expf(s[j][r] - mnew);
                    s[j][r] = p;
                    ls += p;
                }
            }
            ls += __shfl_xor_sync(0xffffffffu, ls, 1);
            ls += __shfl_xor_sync(0xffffffffu, ls, 2);
            l_i[r2] = l_i[r2] * alpha + ls;

            #pragma unroll
            for (int j = 0; j < 16; j++) {
                o[j][r2 * 2 + 0] *= alpha;
                o[j][r2 * 2 + 1] *= alpha;
            }
        }

        // P -> smem (fp16 pairs, per-warp rows)
        {
            int base0 = (wid * 16 + g) * PPW;
            int base1 = (wid * 16 + g + 8) * PPW;
            #pragma unroll
            for (int j = 0; j < 8; j++) {
                Ps[base0 + j * 4 + tig] = packh2(s[j][0], s[j][1]);
                Ps[base1 + j * 4 + tig] = packh2(s[j][2], s[j][3]);
            }
        }
        __syncwarp();

        asm volatile("cp.async.wait_group 0;\n" ::: "memory");  // V ready
        __syncthreads();                                        // done with K

        if (kt + 1 < nkt) issueK(kt + 1);
        else asm volatile("cp.async.commit_group;\n" ::: "memory");

        // O += P V : m16 x n128, k=64 (4 x k16); V d-major
        #pragma unroll
        for (int kk = 0; kk < 4; kk++) {
            unsigned a[4];
            int r0 = (wid * 16 + g) * PPW + kk * 8 + tig;
            a[0] = Ps[r0];          a[1] = Ps[r0 + 8 * PPW];
            a[2] = Ps[r0 + 4];      a[3] = Ps[r0 + 8 * PPW + 4];
            #pragma unroll
            for (int j = 0; j < 16; j++) {
                unsigned bq[2];
                int rb = (j * 8 + g) * VPW + kk * 8 + tig;
                bq[0] = Vs[rb]; bq[1] = Vs[rb + 4];
                mma_f16(o[j], a, bq);
            }
        }

        __syncthreads();
        if (kt + 1 < nkt) issueV(kt + 1);
        else asm volatile("cp.async.commit_group;\n" ::: "memory");
    }

    const float inv0 = 1.f / l_i[0];
    const float inv1 = 1.f / l_i[1];
    #pragma unroll
    for (int j = 0; j < 16; j++) {
        int d = j * 8 + 2 * tig;
        size_t base0 = ((size_t)(b * T_ + qrow0    )) * C_ + h * HS_ + d;
        size_t base1 = ((size_t)(b * T_ + qrow0 + 8)) * C_ + h * HS_ + d;
        st_h2(ao + base0, o[j][0] * inv0, o[j][1] * inv0);
        st_h2(ao + base1, o[j][2] * inv1, o[j][3] * inv1);
    }
}

// ---------------------------------------------------------------------------
// Launch
// ---------------------------------------------------------------------------
extern "C" void kernel_launch(void* const* d_in, const int* in_sizes, int n_in,
                              void* d_out, int out_size)
{
    const float* x    = (const float*)d_in[0];
    const float* fc   = (const float*)d_in[1];
    const float* fs   = (const float*)d_in[2];
    const float* Wdq  = (const float*)d_in[3];
    const float* Wuq  = (const float*)d_in[4];
    const float* Wdkv = (const float*)d_in[5];
    const float* Wuk  = (const float*)d_in[6];
    const float* Wuv  = (const float*)d_in[7];
    const float* Wqr  = (const float*)d_in[8];
    const float* Wkr  = (const float*)d_in[9];
    const float* Wo   = (const float*)d_in[10];
    float* out = (float*)d_out;

    __half *xh, *wh, *cq, *ckv, *q, *k, *v, *ao;
    cudaGetSymbolAddress((void**)&xh,  g_xh);
    cudaGetSymbolAddress((void**)&wh,  g_wh);
    cudaGetSymbolAddress((void**)&cq,  g_cq);
    cudaGetSymbolAddress((void**)&ckv, g_ckv);
    cudaGetSymbolAddress((void**)&q,   g_q);
    cudaGetSymbolAddress((void**)&k,   g_k);
    cudaGetSymbolAddress((void**)&v,   g_v);
    cudaGetSymbolAddress((void**)&ao,  g_ao);

    static bool attr_set = false;
    if (!attr_set) {
        cudaFuncSetAttribute(flash_attn, cudaFuncAttributeMaxDynamicSharedMemorySize,
                             FLASH_SMEM_BYTES);
        cudaFuncSetAttribute(gemmh<0>, cudaFuncAttributeMaxDynamicSharedMemorySize,
                             GEMM_SMEM_BYTES);
        cudaFuncSetAttribute(gemmh<5>, cudaFuncAttributeMaxDynamicSharedMemorySize,
                             GEMM_SMEM_BYTES);
        cudaFuncSetAttribute(gemmh<8>, cudaFuncAttributeMaxDynamicSharedMemorySize,
                             GEMM_SMEM_BYTES);
        attr_set = true;
    }

    dim3 blk(256);
    const int HUGE = 1 << 29;

    // Convert x + weights to fp16 (4,620,288 float4 slots)
    preconv<<<(4620288 + 255) / 256, 256>>>(
        (const float4*)x, (const float4*)Wdq, (const float4*)Wdkv,
        (const float4*)Wkr, (const float4*)Wuq, (const float4*)Wqr,
        (const float4*)Wuk, (const float4*)Wuv, (const float4*)Wo);

    // GEMM A: x -> [c_q | c_kv | rope-bcast k_r], N=1088, K=2048
    gemmh<5><<<dim3(9, 32), blk, GEMM_SMEM_BYTES>>>(
        xh, xh, HUGE,
        wh + OFF_WDQ, wh + OFF_WDKV, wh + OFF_WKR, wh + OFF_WKR,
        512, 1024, 1088,
        1088, C_, C_, C_, nullptr, 0, fc, fs);

    // GEMM B+C merged: [cq|ckv] -> [q_c | rope q_r | k_c | v], N=7168, K=512
    gemmh<8><<<dim3(56, 32), blk, GEMM_SMEM_BYTES>>>(
        cq, ckv, 3072,
        wh + OFF_WUQ, wh + OFF_WQR, wh + OFF_WUK, wh + OFF_WUV,
        2048, 3072, 5120,
        7168, NLQ_, NLQ_, NLQ_, nullptr, 0, fc, fs);

    // Fused flash attention (fp16 operands)
    dim3 gfa(B_ * H_, T_ / 128);
    flash_attn<<<gfa, 256, FLASH_SMEM_BYTES>>>(q, k, v, ao);

    // Output projection (fp16 in, fp32 out): N=2048, K=2048, lda=ldb=2048
    gemmh<0><<<dim3(16, 32), blk, GEMM_SMEM_BYTES>>>(
        ao, ao, HUGE,
        wh + OFF_WO, wh + OFF_WO, wh + OFF_WO, wh + OFF_WO,
        HUGE, HUGE, HUGE,
        2048, C_, C_, C_, out, C_, fc, fs);
}

// round 15
// speedup vs baseline: 2.0432x; 1.0500x over previous
#include <cuda_runtime.h>
#include <cuda_fp16.h>
#include <math.h>
#include <stdint.h>

#define B_   2
#define T_   2048
#define C_   2048
#define H_   16
#define HS_  128
#define NLQ_ 512
#define NLKV_ 512
#define RHD_ 64
#define D_   192

// Scratch (all operands fp16)
__device__ __half g_xh[B_*T_*C_];
__device__ __half g_wh[10092544];
__device__ __half g_cq [B_*T_*NLQ_];
__device__ __half g_ckv[B_*T_*NLKV_];
__device__ __half g_q  [B_*H_*T_*D_];     // (b,h,t,192)
__device__ __half g_k  [B_*H_*T_*D_];     // (b,h,t,192)
__device__ __half g_v  [B_*H_*HS_*T_];    // (b,h,d,t)  d-major for PV fragments
__device__ __half g_ao [B_*T_*C_];        // (b,t,h*hs)

// half offsets into g_wh
#define OFF_WDQ  0
#define OFF_WDKV 1048576
#define OFF_WKR  2097152
#define OFF_WUQ  2228224
#define OFF_WQR  3276800
#define OFF_WUK  3801088
#define OFF_WUV  4849664
#define OFF_WO   5898240

__device__ __forceinline__ void mma_f16(float* d, const unsigned* a, const unsigned* b) {
    asm volatile(
        "mma.sync.aligned.m16n8k16.row.col.f32.f16.f16.f32 "
        "{%0,%1,%2,%3}, {%4,%5,%6,%7}, {%8,%9}, {%0,%1,%2,%3};"
        : "+f"(d[0]), "+f"(d[1]), "+f"(d[2]), "+f"(d[3])
        : "r"(a[0]), "r"(a[1]), "r"(a[2]), "r"(a[3]), "r"(b[0]), "r"(b[1]));
}
__device__ __forceinline__ void ldsm4(unsigned* r, unsigned addr) {
    asm volatile("ldmatrix.sync.aligned.m8n8.x4.shared.b16 {%0,%1,%2,%3}, [%4];"
        : "=r"(r[0]), "=r"(r[1]), "=r"(r[2]), "=r"(r[3]) : "r"(addr));
}
__device__ __forceinline__ void cp16(void* dst, const void* src, bool valid) {
    unsigned d = (unsigned)__cvta_generic_to_shared(dst);
    int sz = valid ? 16 : 0;
    asm volatile("cp.async.cg.shared.global [%0], [%1], 16, %2;\n"
                 :: "r"(d), "l"(src), "r"(sz) : "memory");
}
__device__ __forceinline__ unsigned packh2(float a, float b) {
    __half2 h = __floats2half2_rn(a, b);
    return *(unsigned*)&h;
}
__device__ __forceinline__ void st_h2(__half* p, float a, float b) {
    *(__half2*)p = __floats2half2_rn(a, b);
}

// ---------------------------------------------------------------------------
// Pre-convert: fp32 x + all weights -> fp16 scratch.
// ---------------------------------------------------------------------------
__global__ void __launch_bounds__(256)
preconv(const float4* __restrict__ x,
        const float4* __restrict__ wdq, const float4* __restrict__ wdkv,
        const float4* __restrict__ wkr, const float4* __restrict__ wuq,
        const float4* __restrict__ wqr, const float4* __restrict__ wuk,
        const float4* __restrict__ wuv, const float4* __restrict__ wo)
{
    int i = blockIdx.x * blockDim.x + threadIdx.x;
    const float4* s;
    __half* d;
    if (i < 2097152) {
        s = x + i;
        d = g_xh + (size_t)i * 4;
    } else {
        int j = i - 2097152;
        if (j >= 2523136) return;
        if      (j <  262144) s = wdq  + j;
        else if (j <  524288) s = wdkv + (j -  262144);
        else if (j <  557056) s = wkr  + (j -  524288);
        else if (j <  819200) s = wuq  + (j -  557056);
        else if (j <  950272) s = wqr  + (j -  819200);
        else if (j < 1212416) s = wuk  + (j -  950272);
        else if (j < 1474560) s = wuv  + (j - 1212416);
        else                  s = wo   + (j - 1474560);
        d = g_wh + (size_t)j * 4;
    }
    float4 v = *s;
    __half2 lo = __floats2half2_rn(v.x, v.y);
    __half2 hi = __floats2half2_rn(v.z, v.w);
    *(uint2*)d = make_uint2(*(unsigned*)&lo, *(unsigned*)&hi);
}

// ---------------------------------------------------------------------------
// 3-stage cp.async fp16 GEMM (m16n8k16 + ldmatrix), NT. 256 thr, 8 warps
// 4m x 2n, warp tile m32 x n64, K-tile 64 halfs. M fixed = 4096.
// MODE 0: float Cout ; MODE 5: x-proj split ; MODE 8: merged up-proj.
// ---------------------------------------------------------------------------
#define KPW 36
#define STGW (2 * 128 * KPW)                 // 9216 words / stage
#define GEMM_SMEM_BYTES (3 * STGW * 4)       // 110592

template<int MODE>
__global__ void __launch_bounds__(256, 2)
gemmh(const __half* __restrict__ A0, const __half* __restrict__ A1, int aSplit,
      const __half* __restrict__ B0, const __half* __restrict__ B1,
      const __half* __restrict__ B2, const __half* __restrict__ B3,
      int nb1, int nb2, int nb3,
      int N, int K, int lda, int ldb,
      float* __restrict__ Cout, int ldc,
      const float* __restrict__ fc, const float* __restrict__ fs)
{
    extern __shared__ unsigned gsm[];
    const unsigned sG = (unsigned)__cvta_generic_to_shared(gsm);

    const int m0 = blockIdx.y * 128;
    const int n0 = blockIdx.x * 128;
    const __half* A = (n0 < aSplit) ? A0 : A1;

    const int tid  = threadIdx.x;
    const int wid  = tid >> 5;
    const int lane = tid & 31;
    const int g    = lane >> 2;
    const int tig  = lane & 3;
    const int wr   = (wid & 3) * 32;
    const int wc   = (wid >> 2) * 64;
    const int lrow = tid >> 3;          // 0..31
    const int lkh  = (tid & 7) * 8;     // half offset 0..56
    const int nk   = K / 64;

    // ldmatrix per-lane row/word selectors
    const int la15 = lane & 15;
    const int aW   = (lane >> 4) * 4;
    const int bR   = ((lane >> 4) & 1) * 8 + (lane & 7);
    const int bW   = ((lane >> 3) & 1) * 4;

    float acc[2][8][4];
    #pragma unroll
    for (int i = 0; i < 2; i++)
        #pragma unroll
        for (int j = 0; j < 8; j++)
            #pragma unroll
            for (int r = 0; r < 4; r++) acc[i][j][r] = 0.f;

    auto issue = [&](int kt) {
        unsigned* SA = gsm + (kt % 3) * STGW;
        unsigned* SB = SA + 128 * KPW;
        #pragma unroll
        for (int i = 0; i < 4; i++) {
            int r = lrow + i * 32;
            cp16(SA + r * KPW + (lkh >> 1),
                 A + (size_t)(m0 + r) * lda + kt * 64 + lkh, true);
            int br = n0 + r;
            const __half* bp = (br < nb1) ? B0 + (size_t)br * ldb
                             : (br < nb2) ? B1 + (size_t)(br - nb1) * ldb
                             : (br < nb3) ? B2 + (size_t)(br - nb2) * ldb
                                          : B3 + (size_t)(br - nb3) * ldb;
            cp16(SB + r * KPW + (lkh >> 1), bp + kt * 64 + lkh, br < N);
        }
        asm volatile("cp.async.commit_group;\n" ::: "memory");
    };

    issue(0); issue(1);
    asm volatile("cp.async.wait_group 1;\n" ::: "memory");
    __syncthreads();

    for (int kt = 0; kt < nk; kt++) {
        if (kt + 2 < nk) issue(kt + 2);
        else asm volatile("cp.async.commit_group;\n" ::: "memory");

        const unsigned abase = sG + (unsigned)((kt % 3) * STGW) * 4u;
        const unsigned bbase = abase + 128u * KPW * 4u;
        #pragma unroll
        for (int kk = 0; kk < 4; kk++) {
            unsigned af[2][4];
            ldsm4(af[0], abase + (unsigned)(((wr      + la15) * KPW + kk * 8 + aW) * 4));
            ldsm4(af[1], abase + (unsigned)(((wr + 16 + la15) * KPW + kk * 8 + aW) * 4));
            #pragma unroll
            for (int jp = 0; jp < 4; jp++) {
                unsigned bfr[4];
                ldsm4(bfr, bbase + (unsigned)(((wc + jp * 16 + bR) * KPW + kk * 8 + bW) * 4));
                #pragma unroll
                for (int ti = 0; ti < 2; ti++) {
                    mma_f16(acc[ti][jp * 2    ], af[ti], bfr);
                    mma_f16(acc[ti][jp * 2 + 1], af[ti], bfr + 2);
                }
            }
        }
        asm volatile("cp.async.wait_group 1;\n" ::: "memory");
        __syncthreads();
    }

    #pragma unroll
    for (int ti = 0; ti < 2; ti++) {
        #pragma unroll
        for (int rh = 0; rh < 2; rh++) {
            int gm = m0 + wr + ti * 16 + g + rh * 8;
            int bb = gm >> 11;
            int tt = gm & (T_ - 1);
            #pragma unroll
            for (int tj = 0; tj < 8; tj++) {
                int gn = n0 + wc + tj * 8 + tig * 2;
                float v0 = acc[ti][tj][rh * 2 + 0];
                float v1 = acc[ti][tj][rh * 2 + 1];
                if (MODE == 0) {
                    if (gn < N)
                        *(float2*)(Cout + (size_t)gm * ldc + gn) = make_float2(v0, v1);
                } else if (MODE == 5) {
                    if (gn < 512) {
                        st_h2(g_cq + (size_t)gm * 512 + gn, v0, v1);
                    } else if (gn < 1024) {
                        st_h2(g_ckv + (size_t)gm * 512 + gn - 512, v0, v1);
                    } else if (gn < 1088) {
                        int j = gn - 1024;
                        int p = j >> 1;
                        float c = fc[tt * 32 + p], s = fs[tt * 32 + p];
                        float o0 = v0 * c - v1 * s;
                        float o1 = v0 * s + v1 * c;
                        #pragma unroll
                        for (int hh = 0; hh < H_; hh++)
                            st_h2(g_k + ((size_t)(bb * H_ + hh) * T_ + tt) * D_ + HS_ + j, o0, o1);
                    }
                } else if (MODE == 8) {
                    if (gn < 2048) {
                        int hh = gn >> 7, dd = gn & 127;
                        st_h2(g_q + ((size_t)(bb * H_ + hh) * T_ + tt) * D_ + dd, v0, v1);
                    } else if (gn < 3072) {
                        int j2 = gn - 2048;
                        int hh = j2 >> 6, jj = j2 & 63;
                        int p = jj >> 1;
                        float c = fc[tt * 32 + p], s = fs[tt * 32 + p];
                        st_h2(g_q + ((size_t)(bb * H_ + hh) * T_ + tt) * D_ + HS_ + jj,
                              v0 * c - v1 * s, v0 * s + v1 * c);
                    } else if (gn < 5120) {
                        int t2 = gn - 3072;
                        int hh = t2 >> 7, dd = t2 & 127;
                        st_h2(g_k + ((size_t)(bb * H_ + hh) * T_ + tt) * D_ + dd, v0, v1);
                    } else {
                        int t3 = gn - 5120;
                        int hh = t3 >> 7, dd = t3 & 127;
                        __half* vp = g_v + ((size_t)(bb * H_ + hh) * HS_ + dd) * T_ + tt;
                        vp[0]  = __float2half(v0);
                        vp[T_] = __float2half(v1);
                    }
                }
            }
        }
    }
}

// ---------------------------------------------------------------------------
// Fused flash attention, fp16 (m16n8k16 + ldmatrix), fp32 softmax/accum.
// Q [128][100w], K [64][100w], V d-major [128][36w], P [128][36w].
// ---------------------------------------------------------------------------
#define QPW  100
#define KPW2 100
#define VPW  36
#define PPW  36
#define FLASH_SMEM_WORDS (128*QPW + 64*KPW2 + 128*VPW + 128*PPW)  // 28416
#define FLASH_SMEM_BYTES (FLASH_SMEM_WORDS * 4)                   // 113664

__global__ void __launch_bounds__(256, 1)
flash_attn(const __half* __restrict__ qg, const __half* __restrict__ kg,
           const __half* __restrict__ vg, __half* __restrict__ ao)
{
    extern __shared__ unsigned smu[];
    unsigned* Qs = smu;
    unsigned* Ks = Qs + 128 * QPW;
    unsigned* Vs = Ks + 64 * KPW2;
    unsigned* Ps = Vs + 128 * VPW;
    const unsigned sQ = (unsigned)__cvta_generic_to_shared(Qs);
    const unsigned sK = (unsigned)__cvta_generic_to_shared(Ks);
    const unsigned sV = (unsigned)__cvta_generic_to_shared(Vs);
    const unsigned sP = (unsigned)__cvta_generic_to_shared(Ps);

    const int z  = blockIdx.x;
    const int iy = (int)gridDim.y - 1 - blockIdx.y;
    const int q0 = iy * 128;
    const int b = z / H_, h = z % H_;

    const __half* Qg = qg + (size_t)z * T_ * D_;
    const __half* Kg = kg + (size_t)z * T_ * D_;
    const __half* Vg = vg + (size_t)z * HS_ * T_;   // (d, t)

    const int tid = threadIdx.x;
    const int wid = tid >> 5, lane = tid & 31;
    const int g = lane >> 2, tig = lane & 3;
    const int qrow0 = q0 + wid * 16 + g;

    // ldmatrix per-lane selectors
    const int la15 = lane & 15;
    const int aW   = (lane >> 4) * 4;
    const int bR   = ((lane >> 4) & 1) * 8 + (lane & 7);
    const int bW   = ((lane >> 3) & 1) * 4;

    auto issueK = [&](int kt) {
        #pragma unroll
        for (int it = 0; it < 6; it++) {
            int idx = tid + it * 256;
            int row = idx / 24, kh = (idx % 24) * 8;
            cp16(Ks + row * KPW2 + (kh >> 1),
                 Kg + (size_t)(kt * 64 + row) * D_ + kh, true);
        }
        asm volatile("cp.async.commit_group;\n" ::: "memory");
    };
    auto issueV = [&](int kt) {
        #pragma unroll
        for (int it = 0; it < 4; it++) {
            int idx = tid + it * 256;
            int dd = idx / 8, kh = (idx % 8) * 8;
            cp16(Vs + dd * VPW + (kh >> 1),
                 Vg + (size_t)dd * T_ + kt * 64 + kh, true);
        }
        asm volatile("cp.async.commit_group;\n" ::: "memory");
    };

    #pragma unroll
    for (int it = 0; it < 12; it++) {
        int idx = tid + it * 256;
        int row = idx / 24, kh = (idx % 24) * 8;
        cp16(Qs + row * QPW + (kh >> 1),
             Qg + (size_t)(q0 + row) * D_ + kh, true);
    }
    issueK(0);
    issueV(0);

    float m_i[2] = {-1e30f, -1e30f};
    float l_i[2] = {0.f, 0.f};
    float o[16][4];
    #pragma unroll
    for (int j = 0; j < 16; j++)
        #pragma unroll
        for (int r = 0; r < 4; r++) o[j][r] = 0.f;

    const int nkt = 2 * iy + 2;
    const float scale = 0.07216878364870323f;

    for (int kt = 0; kt < nkt; kt++) {
        asm volatile("cp.async.wait_group 1;\n" ::: "memory");  // Q+K ready
        __syncthreads();

        // S = Q K^T : m16 x n64, k=192 (12 x k16)
        float s[8][4];
        #pragma unroll
        for (int j = 0; j < 8; j++)
            #pragma unroll
            for (int r = 0; r < 4; r++) s[j][r] = 0.f;

        #pragma unroll
        for (int kk = 0; kk < 12; kk++) {
            unsigned a[4];
            ldsm4(a, sQ + (unsigned)(((wid * 16 + la15) * QPW + kk * 8 + aW) * 4));
            #pragma unroll
            for (int jp = 0; jp < 4; jp++) {
                unsigned bfr[4];
                ldsm4(bfr, sK + (unsigned)(((jp * 16 + bR) * KPW2 + kk * 8 + bW) * 4));
                mma_f16(s[jp * 2    ], a, bfr);
                mma_f16(s[jp * 2 + 1], a, bfr + 2);
            }
        }

        // Online softmax (fp32)
        const bool diag = (kt >= 2 * iy);
        #pragma unroll
        for (int r2 = 0; r2 < 2; r2++) {
            const int row = qrow0 + r2 * 8;
            float mx = -1e30f;
            #pragma unroll
            for (int j = 0; j < 8; j++) {
                #pragma unroll
                for (int c = 0; c < 2; c++) {
                    int r = r2 * 2 + c;
                    float v = s[j][r] * scale;
                    if (diag) {
                        int col = kt * 64 + j * 8 + 2 * tig + c;
                        if (col > row) v = -1e30f;
                    }
                    s[j][r] = v;
                    mx = fmaxf(mx, v);
                }
            }
            mx = fmaxf(mx, __shfl_xor_sync(0xffffffffu, mx, 1));
            mx = fmaxf(mx, __shfl_xor_sync(0xffffffffu, mx, 2));
            float mnew = fmaxf(m_i[r2], mx);
            float alpha = __expf(m_i[r2] - mnew);
            m_i[r2] = mnew;

            float ls = 0.f;
            #pragma unroll
            for (int j = 0; j < 8; j++) {
                #pragma unroll
                for (int c = 0; c < 2; c++) {
                    int r = r2 * 2 + c;
                    float p = __expf(s[j][r] - mnew);
                    s[j][r] = p;
                    ls += p;
                }
            }
            ls += __shfl_xor_sync(0xffffffffu, ls, 1);
            ls += __shfl_xor_sync(0xffffffffu, ls, 2);
            l_i[r2] = l_i[r2] * alpha + ls;

            #pragma unroll
            for (int j = 0; j < 16; j++) {
                o[j][r2 * 2 + 0] *= alpha;
                o[j][r2 * 2 + 1] *= alpha;
            }
        }

        // P -> smem (fp16 pairs, per-warp rows)
        {
            int base0 = (wid * 16 + g) * PPW;
            int base1 = (wid * 16 + g + 8) * PPW;
            #pragma unroll
            for (int j = 0; j < 8; j++) {
                Ps[base0 + j * 4 + tig] = packh2(s[j][0], s[j][1]);
                Ps[base1 + j * 4 + tig] = packh2(s[j][2], s[j][3]);
            }
        }
        __syncwarp();

        asm volatile("cp.async.wait_group 0;\n" ::: "memory");  // V ready
        __syncthreads();                                        // done with K

        if (kt + 1 < nkt) issueK(kt + 1);
        else asm volatile("cp.async.commit_group;\n" ::: "memory");

        // O += P V : m16 x n128, k=64 (4 x k16); V d-major
        #pragma unroll
        for (int kk = 0; kk < 4; kk++) {
            unsigned a[4];
            ldsm4(a, sP + (unsigned)(((wid * 16 + la15) * PPW + kk * 8 + aW) * 4));
            #pragma unroll
            for (int jp = 0; jp < 8; jp++) {
                unsigned bfr[4];
                ldsm4(bfr, sV + (unsigned)(((jp * 16 + bR) * VPW + kk * 8 + bW) * 4));
                mma_f16(o[jp * 2    ], a, bfr);
                mma_f16(o[jp * 2 + 1], a, bfr + 2);
            }
        }

        __syncthreads();
        if (kt + 1 < nkt) issueV(kt + 1);
        else asm volatile("cp.async.commit_group;\n" ::: "memory");
    }

    const float inv0 = 1.f / l_i[0];
    const float inv1 = 1.f / l_i[1];
    #pragma unroll
    for (int j = 0; j < 16; j++) {
        int d = j * 8 + 2 * tig;
        size_t base0 = ((size_t)(b * T_ + qrow0    )) * C_ + h * HS_ + d;
        size_t base1 = ((size_t)(b * T_ + qrow0 + 8)) * C_ + h * HS_ + d;
        st_h2(ao + base0, o[j][0] * inv0, o[j][1] * inv0);
        st_h2(ao + base1, o[j][2] * inv1, o[j][3] * inv1);
    }
}

// ---------------------------------------------------------------------------
// Launch
// ---------------------------------------------------------------------------
extern "C" void kernel_launch(void* const* d_in, const int* in_sizes, int n_in,
                              void* d_out, int out_size)
{
    const float* x    = (const float*)d_in[0];
    const float* fc   = (const float*)d_in[1];
    const float* fs   = (const float*)d_in[2];
    const float* Wdq  = (const float*)d_in[3];
    const float* Wuq  = (const float*)d_in[4];
    const float* Wdkv = (const float*)d_in[5];
    const float* Wuk  = (const float*)d_in[6];
    const float* Wuv  = (const float*)d_in[7];
    const float* Wqr  = (const float*)d_in[8];
    const float* Wkr  = (const float*)d_in[9];
    const float* Wo   = (const float*)d_in[10];
    float* out = (float*)d_out;

    __half *xh, *wh, *cq, *ckv, *q, *k, *v, *ao;
    cudaGetSymbolAddress((void**)&xh,  g_xh);
    cudaGetSymbolAddress((void**)&wh,  g_wh);
    cudaGetSymbolAddress((void**)&cq,  g_cq);
    cudaGetSymbolAddress((void**)&ckv, g_ckv);
    cudaGetSymbolAddress((void**)&q,   g_q);
    cudaGetSymbolAddress((void**)&k,   g_k);
    cudaGetSymbolAddress((void**)&v,   g_v);
    cudaGetSymbolAddress((void**)&ao,  g_ao);

    static bool attr_set = false;
    if (!attr_set) {
        cudaFuncSetAttribute(flash_attn, cudaFuncAttributeMaxDynamicSharedMemorySize,
                             FLASH_SMEM_BYTES);
        cudaFuncSetAttribute(gemmh<0>, cudaFuncAttributeMaxDynamicSharedMemorySize,
                             GEMM_SMEM_BYTES);
        cudaFuncSetAttribute(gemmh<5>, cudaFuncAttributeMaxDynamicSharedMemorySize,
                             GEMM_SMEM_BYTES);
        cudaFuncSetAttribute(gemmh<8>, cudaFuncAttributeMaxDynamicSharedMemorySize,
                             GEMM_SMEM_BYTES);
        attr_set = true;
    }

    dim3 blk(256);
    const int HUGE = 1 << 29;

    // Convert x + weights to fp16
    preconv<<<(4620288 + 255) / 256, 256>>>(
        (const float4*)x, (const float4*)Wdq, (const float4*)Wdkv,
        (const float4*)Wkr, (const float4*)Wuq, (const float4*)Wqr,
        (const float4*)Wuk, (const float4*)Wuv, (const float4*)Wo);

    // GEMM A: x -> [c_q | c_kv | rope-bcast k_r], N=1088, K=2048
    gemmh<5><<<dim3(9, 32), blk, GEMM_SMEM_BYTES>>>(
        xh, xh, HUGE,
        wh + OFF_WDQ, wh + OFF_WDKV, wh + OFF_WKR, wh + OFF_WKR,
        512, 1024, 1088,
        1088, C_, C_, C_, nullptr, 0, fc, fs);

    // GEMM B+C merged: [cq|ckv] -> [q_c | rope q_r | k_c | v], N=7168, K=512
    gemmh<8><<<dim3(56, 32), blk, GEMM_SMEM_BYTES>>>(
        cq, ckv, 3072,
        wh + OFF_WUQ, wh + OFF_WQR, wh + OFF_WUK, wh + OFF_WUV,
        2048, 3072, 5120,
        7168, NLQ_, NLQ_, NLQ_, nullptr, 0, fc, fs);

    // Fused flash attention (fp16 operands)
    dim3 gfa(B_ * H_, T_ / 128);
    flash_attn<<<gfa, 256, FLASH_SMEM_BYTES>>>(q, k, v, ao);

    // Output projection (fp16 in, fp32 out)
    gemmh<0><<<dim3(16, 32), blk, GEMM_SMEM_BYTES>>>(
        ao, ao, HUGE,
        wh + OFF_WO, wh + OFF_WO, wh + OFF_WO, wh + OFF_WO,
        HUGE, HUGE, HUGE,
        2048, C_, C_, C_, out, C_, fc, fs);
}

// round 16
// speedup vs baseline: 2.0958x; 1.0258x over previous
#include <cuda_runtime.h>
#include <cuda_fp16.h>
#include <math.h>
#include <stdint.h>

#define B_   2
#define T_   2048
#define C_   2048
#define H_   16
#define HS_  128
#define NLQ_ 512
#define NLKV_ 512
#define RHD_ 64
#define D_   192

// scale/sqrt(192) * log2(e), folded into Q at projection time
#define QSC 0.10412706636369057f

// Scratch (all operands fp16)
__device__ __half g_xh[B_*T_*C_];
__device__ __half g_wh[10092544];
__device__ __half g_cq [B_*T_*NLQ_];
__device__ __half g_ckv[B_*T_*NLKV_];
__device__ __half g_q  [B_*H_*T_*D_];     // (b,h,t,192), pre-scaled by QSC
__device__ __half g_k  [B_*H_*T_*D_];     // (b,h,t,192)
__device__ __half g_v  [B_*H_*HS_*T_];    // (b,h,d,t)  d-major for PV fragments
__device__ __half g_ao [B_*T_*C_];        // (b,t,h*hs)

// half offsets into g_wh
#define OFF_WDQ  0
#define OFF_WDKV 1048576
#define OFF_WKR  2097152
#define OFF_WUQ  2228224
#define OFF_WQR  3276800
#define OFF_WUK  3801088
#define OFF_WUV  4849664
#define OFF_WO   5898240

__device__ __forceinline__ void mma_f16(float* d, const unsigned* a, const unsigned* b) {
    asm volatile(
        "mma.sync.aligned.m16n8k16.row.col.f32.f16.f16.f32 "
        "{%0,%1,%2,%3}, {%4,%5,%6,%7}, {%8,%9}, {%0,%1,%2,%3};"
        : "+f"(d[0]), "+f"(d[1]), "+f"(d[2]), "+f"(d[3])
        : "r"(a[0]), "r"(a[1]), "r"(a[2]), "r"(a[3]), "r"(b[0]), "r"(b[1]));
}
__device__ __forceinline__ void ldsm4(unsigned* r, unsigned addr) {
    asm volatile("ldmatrix.sync.aligned.m8n8.x4.shared.b16 {%0,%1,%2,%3}, [%4];"
        : "=r"(r[0]), "=r"(r[1]), "=r"(r[2]), "=r"(r[3]) : "r"(addr));
}
__device__ __forceinline__ void cp16(void* dst, const void* src, bool valid) {
    unsigned d = (unsigned)__cvta_generic_to_shared(dst);
    int sz = valid ? 16 : 0;
    asm volatile("cp.async.cg.shared.global [%0], [%1], 16, %2;\n"
                 :: "r"(d), "l"(src), "r"(sz) : "memory");
}
__device__ __forceinline__ unsigned packh2(float a, float b) {
    __half2 h = __floats2half2_rn(a, b);
    return *(unsigned*)&h;
}
__device__ __forceinline__ void st_h2(__half* p, float a, float b) {
    *(__half2*)p = __floats2half2_rn(a, b);
}

// ---------------------------------------------------------------------------
// Pre-convert: fp32 x + all weights -> fp16 scratch.
// ---------------------------------------------------------------------------
__global__ void __launch_bounds__(256)
preconv(const float4* __restrict__ x,
        const float4* __restrict__ wdq, const float4* __restrict__ wdkv,
        const float4* __restrict__ wkr, const float4* __restrict__ wuq,
        const float4* __restrict__ wqr, const float4* __restrict__ wuk,
        const float4* __restrict__ wuv, const float4* __restrict__ wo)
{
    int i = blockIdx.x * blockDim.x + threadIdx.x;
    const float4* s;
    __half* d;
    if (i < 2097152) {
        s = x + i;
        d = g_xh + (size_t)i * 4;
    } else {
        int j = i - 2097152;
        if (j >= 2523136) return;
        if      (j <  262144) s = wdq  + j;
        else if (j <  524288) s = wdkv + (j -  262144);
        else if (j <  557056) s = wkr  + (j -  524288);
        else if (j <  819200) s = wuq  + (j -  557056);
        else if (j <  950272) s = wqr  + (j -  819200);
        else if (j < 1212416) s = wuk  + (j -  950272);
        else if (j < 1474560) s = wuv  + (j - 1212416);
        else                  s = wo   + (j - 1474560);
        d = g_wh + (size_t)j * 4;
    }
    float4 v = *s;
    __half2 lo = __floats2half2_rn(v.x, v.y);
    __half2 hi = __floats2half2_rn(v.z, v.w);
    *(uint2*)d = make_uint2(*(unsigned*)&lo, *(unsigned*)&hi);
}

// ---------------------------------------------------------------------------
// 3-stage cp.async fp16 GEMM (m16n8k16 + ldmatrix), NT. 256 thr, 8 warps
// 4m x 2n, warp tile m32 x n64, K-tile 64 halfs. M fixed = 4096.
// MODE 0: float Cout ; MODE 5: x-proj split ; MODE 8: merged up-proj
// (q outputs pre-scaled by QSC).
// ---------------------------------------------------------------------------
#define KPW 36
#define STGW (2 * 128 * KPW)                 // 9216 words / stage
#define GEMM_SMEM_BYTES (3 * STGW * 4)       // 110592

template<int MODE>
__global__ void __launch_bounds__(256, 2)
gemmh(const __half* __restrict__ A0, const __half* __restrict__ A1, int aSplit,
      const __half* __restrict__ B0, const __half* __restrict__ B1,
      const __half* __restrict__ B2, const __half* __restrict__ B3,
      int nb1, int nb2, int nb3,
      int N, int K, int lda, int ldb,
      float* __restrict__ Cout, int ldc,
      const float* __restrict__ fc, const float* __restrict__ fs)
{
    extern __shared__ unsigned gsm[];
    const unsigned sG = (unsigned)__cvta_generic_to_shared(gsm);

    const int m0 = blockIdx.y * 128;
    const int n0 = blockIdx.x * 128;
    const __half* A = (n0 < aSplit) ? A0 : A1;

    const int tid  = threadIdx.x;
    const int wid  = tid >> 5;
    const int lane = tid & 31;
    const int g    = lane >> 2;
    const int tig  = lane & 3;
    const int wr   = (wid & 3) * 32;
    const int wc   = (wid >> 2) * 64;
    const int lrow = tid >> 3;          // 0..31
    const int lkh  = (tid & 7) * 8;     // half offset 0..56
    const int nk   = K / 64;

    const int la15 = lane & 15;
    const int aW   = (lane >> 4) * 4;
    const int bR   = ((lane >> 4) & 1) * 8 + (lane & 7);
    const int bW   = ((lane >> 3) & 1) * 4;

    float acc[2][8][4];
    #pragma unroll
    for (int i = 0; i < 2; i++)
        #pragma unroll
        for (int j = 0; j < 8; j++)
            #pragma unroll
            for (int r = 0; r < 4; r++) acc[i][j][r] = 0.f;

    auto issue = [&](int kt) {
        unsigned* SA = gsm + (kt % 3) * STGW;
        unsigned* SB = SA + 128 * KPW;
        #pragma unroll
        for (int i = 0; i < 4; i++) {
            int r = lrow + i * 32;
            cp16(SA + r * KPW + (lkh >> 1),
                 A + (size_t)(m0 + r) * lda + kt * 64 + lkh, true);
            int br = n0 + r;
            const __half* bp = (br < nb1) ? B0 + (size_t)br * ldb
                             : (br < nb2) ? B1 + (size_t)(br - nb1) * ldb
                             : (br < nb3) ? B2 + (size_t)(br - nb2) * ldb
                                          : B3 + (size_t)(br - nb3) * ldb;
            cp16(SB + r * KPW + (lkh >> 1), bp + kt * 64 + lkh, br < N);
        }
        asm volatile("cp.async.commit_group;\n" ::: "memory");
    };

    issue(0); issue(1);
    asm volatile("cp.async.wait_group 1;\n" ::: "memory");
    __syncthreads();

    for (int kt = 0; kt < nk; kt++) {
        if (kt + 2 < nk) issue(kt + 2);
        else asm volatile("cp.async.commit_group;\n" ::: "memory");

        const unsigned abase = sG + (unsigned)((kt % 3) * STGW) * 4u;
        const unsigned bbase = abase + 128u * KPW * 4u;
        #pragma unroll
        for (int kk = 0; kk < 4; kk++) {
            unsigned af[2][4];
            ldsm4(af[0], abase + (unsigned)(((wr      + la15) * KPW + kk * 8 + aW) * 4));
            ldsm4(af[1], abase + (unsigned)(((wr + 16 + la15) * KPW + kk * 8 + aW) * 4));
            #pragma unroll
            for (int jp = 0; jp < 4; jp++) {
                unsigned bfr[4];
                ldsm4(bfr, bbase + (unsigned)(((wc + jp * 16 + bR) * KPW + kk * 8 + bW) * 4));
                #pragma unroll
                for (int ti = 0; ti < 2; ti++) {
                    mma_f16(acc[ti][jp * 2    ], af[ti], bfr);
                    mma_f16(acc[ti][jp * 2 + 1], af[ti], bfr + 2);
                }
            }
        }
        asm volatile("cp.async.wait_group 1;\n" ::: "memory");
        __syncthreads();
    }

    #pragma unroll
    for (int ti = 0; ti < 2; ti++) {
        #pragma unroll
        for (int rh = 0; rh < 2; rh++) {
            int gm = m0 + wr + ti * 16 + g + rh * 8;
            int bb = gm >> 11;
            int tt = gm & (T_ - 1);
            #pragma unroll
            for (int tj = 0; tj < 8; tj++) {
                int gn = n0 + wc + tj * 8 + tig * 2;
                float v0 = acc[ti][tj][rh * 2 + 0];
                float v1 = acc[ti][tj][rh * 2 + 1];
                if (MODE == 0) {
                    if (gn < N)
                        *(float2*)(Cout + (size_t)gm * ldc + gn) = make_float2(v0, v1);
                } else if (MODE == 5) {
                    if (gn < 512) {
                        st_h2(g_cq + (size_t)gm * 512 + gn, v0, v1);
                    } else if (gn < 1024) {
                        st_h2(g_ckv + (size_t)gm * 512 + gn - 512, v0, v1);
                    } else if (gn < 1088) {
                        int j = gn - 1024;
                        int p = j >> 1;
                        float c = fc[tt * 32 + p], s = fs[tt * 32 + p];
                        float o0 = v0 * c - v1 * s;
                        float o1 = v0 * s + v1 * c;
                        #pragma unroll
                        for (int hh = 0; hh < H_; hh++)
                            st_h2(g_k + ((size_t)(bb * H_ + hh) * T_ + tt) * D_ + HS_ + j, o0, o1);
                    }
                } else if (MODE == 8) {
                    if (gn < 2048) {
                        int hh = gn >> 7, dd = gn & 127;
                        st_h2(g_q + ((size_t)(bb * H_ + hh) * T_ + tt) * D_ + dd,
                              v0 * QSC, v1 * QSC);
                    } else if (gn < 3072) {
                        int j2 = gn - 2048;
                        int hh = j2 >> 6, jj = j2 & 63;
                        int p = jj >> 1;
                        float c = fc[tt * 32 + p], s = fs[tt * 32 + p];
                        st_h2(g_q + ((size_t)(bb * H_ + hh) * T_ + tt) * D_ + HS_ + jj,
                              (v0 * c - v1 * s) * QSC, (v0 * s + v1 * c) * QSC);
                    } else if (gn < 5120) {
                        int t2 = gn - 3072;
                        int hh = t2 >> 7, dd = t2 & 127;
                        st_h2(g_k + ((size_t)(bb * H_ + hh) * T_ + tt) * D_ + dd, v0, v1);
                    } else {
                        int t3 = gn - 5120;
                        int hh = t3 >> 7, dd = t3 & 127;
                        __half* vp = g_v + ((size_t)(bb * H_ + hh) * HS_ + dd) * T_ + tt;
                        vp[0]  = __float2half(v0);
                        vp[T_] = __float2half(v1);
                    }
                }
            }
        }
    }
}

// ---------------------------------------------------------------------------
// Fused flash attention, fp16 (m16n8k16 + ldmatrix), fp32 softmax in log2
// domain (Q pre-scaled by scale*log2e). Q fragments hoisted to registers.
// ---------------------------------------------------------------------------
#define QPW  100
#define KPW2 100
#define VPW  36
#define PPW  36
#define FLASH_SMEM_WORDS (128*QPW + 64*KPW2 + 128*VPW + 128*PPW)  // 28416
#define FLASH_SMEM_BYTES (FLASH_SMEM_WORDS * 4)                   // 113664

__global__ void __launch_bounds__(256, 1)
flash_attn(const __half* __restrict__ qg, const __half* __restrict__ kg,
           const __half* __restrict__ vg, __half* __restrict__ ao)
{
    extern __shared__ unsigned smu[];
    unsigned* Qs = smu;
    unsigned* Ks = Qs + 128 * QPW;
    unsigned* Vs = Ks + 64 * KPW2;
    unsigned* Ps = Vs + 128 * VPW;
    const unsigned sQ = (unsigned)__cvta_generic_to_shared(Qs);
    const unsigned sK = (unsigned)__cvta_generic_to_shared(Ks);
    const unsigned sV = (unsigned)__cvta_generic_to_shared(Vs);
    const unsigned sP = (unsigned)__cvta_generic_to_shared(Ps);

    const int z  = blockIdx.x;
    const int iy = (int)gridDim.y - 1 - blockIdx.y;
    const int q0 = iy * 128;
    const int b = z / H_, h = z % H_;

    const __half* Qg = qg + (size_t)z * T_ * D_;
    const __half* Kg = kg + (size_t)z * T_ * D_;
    const __half* Vg = vg + (size_t)z * HS_ * T_;   // (d, t)

    const int tid = threadIdx.x;
    const int wid = tid >> 5, lane = tid & 31;
    const int g = lane >> 2, tig = lane & 3;
    const int qrow0 = q0 + wid * 16 + g;

    const int la15 = lane & 15;
    const int aW   = (lane >> 4) * 4;
    const int bR   = ((lane >> 4) & 1) * 8 + (lane & 7);
    const int bW   = ((lane >> 3) & 1) * 4;

    auto issueK = [&](int kt) {
        #pragma unroll
        for (int it = 0; it < 6; it++) {
            int idx = tid + it * 256;
            int row = idx / 24, kh = (idx % 24) * 8;
            cp16(Ks + row * KPW2 + (kh >> 1),
                 Kg + (size_t)(kt * 64 + row) * D_ + kh, true);
        }
        asm volatile("cp.async.commit_group;\n" ::: "memory");
    };
    auto issueV = [&](int kt) {
        #pragma unroll
        for (int it = 0; it < 4; it++) {
            int idx = tid + it * 256;
            int dd = idx / 8, kh = (idx % 8) * 8;
            cp16(Vs + dd * VPW + (kh >> 1),
                 Vg + (size_t)dd * T_ + kt * 64 + kh, true);
        }
        asm volatile("cp.async.commit_group;\n" ::: "memory");
    };

    #pragma unroll
    for (int it = 0; it < 12; it++) {
        int idx = tid + it * 256;
        int row = idx / 24, kh = (idx % 24) * 8;
        cp16(Qs + row * QPW + (kh >> 1),
             Qg + (size_t)(q0 + row) * D_ + kh, true);
    }
    issueK(0);      // commits Q + K0 as one group
    issueV(0);

    // Hoist Q fragments into registers (Q ready after the Q+K0 group drains)
    asm volatile("cp.async.wait_group 1;\n" ::: "memory");
    __syncthreads();
    unsigned qf[12][4];
    #pragma unroll
    for (int kk = 0; kk < 12; kk++)
        ldsm4(qf[kk], sQ + (unsigned)(((wid * 16 + la15) * QPW + kk * 8 + aW) * 4));

    float m_i[2] = {-1e30f, -1e30f};
    float l_i[2] = {0.f, 0.f};
    float o[16][4];
    #pragma unroll
    for (int j = 0; j < 16; j++)
        #pragma unroll
        for (int r = 0; r < 4; r++) o[j][r] = 0.f;

    const int nkt = 2 * iy + 2;

    for (int kt = 0; kt < nkt; kt++) {
        asm volatile("cp.async.wait_group 1;\n" ::: "memory");  // K(kt) ready
        __syncthreads();

        // S = Q K^T : m16 x n64, k=192 (12 x k16); Q in registers
        float s[8][4];
        #pragma unroll
        for (int j = 0; j < 8; j++)
            #pragma unroll
            for (int r = 0; r < 4; r++) s[j][r] = 0.f;

        #pragma unroll
        for (int kk = 0; kk < 12; kk++) {
            #pragma unroll
            for (int jp = 0; jp < 4; jp++) {
                unsigned bfr[4];
                ldsm4(bfr, sK + (unsigned)(((jp * 16 + bR) * KPW2 + kk * 8 + bW) * 4));
                mma_f16(s[jp * 2    ], qf[kk], bfr);
                mma_f16(s[jp * 2 + 1], qf[kk], bfr + 2);
            }
        }

        // Online softmax (log2 domain; Q carries scale*log2e)
        const bool diag = (kt >= 2 * iy);
        #pragma unroll
        for (int r2 = 0; r2 < 2; r2++) {
            const int row = qrow0 + r2 * 8;
            float mx = -1e30f;
            #pragma unroll
            for (int j = 0; j < 8; j++) {
                #pragma unroll
                for (int c = 0; c < 2; c++) {
                    int r = r2 * 2 + c;
                    float v = s[j][r];
                    if (diag) {
                        int col = kt * 64 + j * 8 + 2 * tig + c;
                        if (col > row) v = -1e30f;
                    }
                    s[j][r] = v;
                    mx = fmaxf(mx, v);
                }
            }
            mx = fmaxf(mx, __shfl_xor_sync(0xffffffffu, mx, 1));
            mx = fmaxf(mx, __shfl_xor_sync(0xffffffffu, mx, 2));
            float mnew = fmaxf(m_i[r2], mx);
            float alpha = exp2f(m_i[r2] - mnew);
            m_i[r2] = mnew;

            float ls = 0.f;
            #pragma unroll
            for (int j = 0; j < 8; j++) {
                #pragma unroll
                for (int c = 0; c < 2; c++) {
                    int r = r2 * 2 + c;
                    float p = exp2f(s[j][r] - mnew);
                    s[j][r] = p;
                    ls += p;
                }
            }
            ls += __shfl_xor_sync(0xffffffffu, ls, 1);
            ls += __shfl_xor_sync(0xffffffffu, ls, 2);
            l_i[r2] = l_i[r2] * alpha + ls;

            #pragma unroll
            for (int j = 0; j < 16; j++) {
                o[j][r2 * 2 + 0] *= alpha;
                o[j][r2 * 2 + 1] *= alpha;
            }
        }

        // P -> smem (fp16 pairs, per-warp rows)
        {
            int base0 = (wid * 16 + g) * PPW;
            int base1 = (wid * 16 + g + 8) * PPW;
            #pragma unroll
            for (int j = 0; j < 8; j++) {
                Ps[base0 + j * 4 + tig] = packh2(s[j][0], s[j][1]);
                Ps[base1 + j * 4 + tig] = packh2(s[j][2], s[j][3]);
            }
        }
        __syncwarp();

        asm volatile("cp.async.wait_group 0;\n" ::: "memory");  // V ready
        __syncthreads();                                        // done with K

        if (kt + 1 < nkt) issueK(kt + 1);
        else asm volatile("cp.async.commit_group;\n" ::: "memory");

        // O += P V : m16 x n128, k=64 (4 x k16); V d-major
        #pragma unroll
        for (int kk = 0; kk < 4; kk++) {
            unsigned a[4];
            ldsm4(a, sP + (unsigned)(((wid * 16 + la15) * PPW + kk * 8 + aW) * 4));
            #pragma unroll
            for (int jp = 0; jp < 8; jp++) {
                unsigned bfr[4];
                ldsm4(bfr, sV + (unsigned)(((jp * 16 + bR) * VPW + kk * 8 + bW) * 4));
                mma_f16(o[jp * 2    ], a, bfr);
                mma_f16(o[jp * 2 + 1], a, bfr + 2);
            }
        }

        __syncthreads();
        if (kt + 1 < nkt) issueV(kt + 1);
        else asm volatile("cp.async.commit_group;\n" ::: "memory");
    }

    const float inv0 = 1.f / l_i[0];
    const float inv1 = 1.f / l_i[1];
    #pragma unroll
    for (int j = 0; j < 16; j++) {
        int d = j * 8 + 2 * tig;
        size_t base0 = ((size_t)(b * T_ + qrow0    )) * C_ + h * HS_ + d;
        size_t base1 = ((size_t)(b * T_ + qrow0 + 8)) * C_ + h * HS_ + d;
        st_h2(ao + base0, o[j][0] * inv0, o[j][1] * inv0);
        st_h2(ao + base1, o[j][2] * inv1, o[j][3] * inv1);
    }
}

// ---------------------------------------------------------------------------
// Launch
// ---------------------------------------------------------------------------
extern "C" void kernel_launch(void* const* d_in, const int* in_sizes, int n_in,
                              void* d_out, int out_size)
{
    const float* x    = (const float*)d_in[0];
    const float* fc   = (const float*)d_in[1];
    const float* fs   = (const float*)d_in[2];
    const float* Wdq  = (const float*)d_in[3];
    const float* Wuq  = (const float*)d_in[4];
    const float* Wdkv = (const float*)d_in[5];
    const float* Wuk  = (const float*)d_in[6];
    const float* Wuv  = (const float*)d_in[7];
    const float* Wqr  = (const float*)d_in[8];
    const float* Wkr  = (const float*)d_in[9];
    const float* Wo   = (const float*)d_in[10];
    float* out = (float*)d_out;

    __half *xh, *wh, *cq, *ckv, *q, *k, *v, *ao;
    cudaGetSymbolAddress((void**)&xh,  g_xh);
    cudaGetSymbolAddress((void**)&wh,  g_wh);
    cudaGetSymbolAddress((void**)&cq,  g_cq);
    cudaGetSymbolAddress((void**)&ckv, g_ckv);
    cudaGetSymbolAddress((void**)&q,   g_q);
    cudaGetSymbolAddress((void**)&k,   g_k);
    cudaGetSymbolAddress((void**)&v,   g_v);
    cudaGetSymbolAddress((void**)&ao,  g_ao);

    static bool attr_set = false;
    if (!attr_set) {
        cudaFuncSetAttribute(flash_attn, cudaFuncAttributeMaxDynamicSharedMemorySize,
                             FLASH_SMEM_BYTES);
        cudaFuncSetAttribute(gemmh<0>, cudaFuncAttributeMaxDynamicSharedMemorySize,
                             GEMM_SMEM_BYTES);
        cudaFuncSetAttribute(gemmh<5>, cudaFuncAttributeMaxDynamicSharedMemorySize,
                             GEMM_SMEM_BYTES);
        cudaFuncSetAttribute(gemmh<8>, cudaFuncAttributeMaxDynamicSharedMemorySize,
                             GEMM_SMEM_BYTES);
        attr_set = true;
    }

    dim3 blk(256);
    const int HUGE = 1 << 29;

    // Convert x + weights to fp16
    preconv<<<(4620288 + 255) / 256, 256>>>(
        (const float4*)x, (const float4*)Wdq, (const float4*)Wdkv,
        (const float4*)Wkr, (const float4*)Wuq, (const float4*)Wqr,
        (const float4*)Wuk, (const float4*)Wuv, (const float4*)Wo);

    // GEMM A: x -> [c_q | c_kv | rope-bcast k_r], N=1088, K=2048
    gemmh<5><<<dim3(9, 32), blk, GEMM_SMEM_BYTES>>>(
        xh, xh, HUGE,
        wh + OFF_WDQ, wh + OFF_WDKV, wh + OFF_WKR, wh + OFF_WKR,
        512, 1024, 1088,
        1088, C_, C_, C_, nullptr, 0, fc, fs);

    // GEMM B+C merged: [cq|ckv] -> [q_c | rope q_r | k_c | v], N=7168, K=512
    gemmh<8><<<dim3(56, 32), blk, GEMM_SMEM_BYTES>>>(
        cq, ckv, 3072,
        wh + OFF_WUQ, wh + OFF_WQR, wh + OFF_WUK, wh + OFF_WUV,
        2048, 3072, 5120,
        7168, NLQ_, NLQ_, NLQ_, nullptr, 0, fc, fs);

    // Fused flash attention (fp16 operands, Q pre-scaled)
    dim3 gfa(B_ * H_, T_ / 128);
    flash_attn<<<gfa, 256, FLASH_SMEM_BYTES>>>(q, k, v, ao);

    // Output projection (fp16 in, fp32 out)
    gemmh<0><<<dim3(16, 32), blk, GEMM_SMEM_BYTES>>>(
        ao, ao, HUGE,
        wh + OFF_WO, wh + OFF_WO, wh + OFF_WO, wh + OFF_WO,
        HUGE, HUGE, HUGE,
        2048, C_, C_, C_, out, C_, fc, fs);
}

// round 17
// speedup vs baseline: 2.1217x; 1.0123x over previous
#include <cuda_runtime.h>
#include <cuda_fp16.h>
#include <math.h>
#include <stdint.h>

#define B_   2
#define T_   2048
#define C_   2048
#define H_   16
#define HS_  128
#define NLQ_ 512
#define NLKV_ 512
#define RHD_ 64
#define D_   192

// 1/sqrt(192) * log2(e), folded into Q at projection time
#define QSC 0.10412706636369057f

// Scratch (all operands fp16)
__device__ __half g_xh[B_*T_*C_];
__device__ __half g_wh[10092544];
__device__ __half g_cq [B_*T_*NLQ_];
__device__ __half g_ckv[B_*T_*NLKV_];
__device__ __half g_q  [B_*H_*T_*D_];     // (b,h,t,192), pre-scaled by QSC
__device__ __half g_k  [B_*H_*T_*D_];     // (b,h,t,192)
__device__ __half g_v  [B_*H_*HS_*T_];    // (b,h,d,t)  d-major for PV fragments
__device__ __half g_ao [B_*T_*C_];        // (b,t,h*hs)

// half offsets into g_wh
#define OFF_WDQ  0
#define OFF_WDKV 1048576
#define OFF_WKR  2097152
#define OFF_WUQ  2228224
#define OFF_WQR  3276800
#define OFF_WUK  3801088
#define OFF_WUV  4849664
#define OFF_WO   5898240

__device__ __forceinline__ void mma_f16(float* d, const unsigned* a, const unsigned* b) {
    asm volatile(
        "mma.sync.aligned.m16n8k16.row.col.f32.f16.f16.f32 "
        "{%0,%1,%2,%3}, {%4,%5,%6,%7}, {%8,%9}, {%0,%1,%2,%3};"
        : "+f"(d[0]), "+f"(d[1]), "+f"(d[2]), "+f"(d[3])
        : "r"(a[0]), "r"(a[1]), "r"(a[2]), "r"(a[3]), "r"(b[0]), "r"(b[1]));
}
__device__ __forceinline__ void ldsm4(unsigned* r, unsigned addr) {
    asm volatile("ldmatrix.sync.aligned.m8n8.x4.shared.b16 {%0,%1,%2,%3}, [%4];"
        : "=r"(r[0]), "=r"(r[1]), "=r"(r[2]), "=r"(r[3]) : "r"(addr));
}
__device__ __forceinline__ void cp16(void* dst, const void* src, bool valid) {
    unsigned d = (unsigned)__cvta_generic_to_shared(dst);
    int sz = valid ? 16 : 0;
    asm volatile("cp.async.cg.shared.global [%0], [%1], 16, %2;\n"
                 :: "r"(d), "l"(src), "r"(sz) : "memory");
}
__device__ __forceinline__ unsigned packh2(float a, float b) {
    __half2 h = __floats2half2_rn(a, b);
    return *(unsigned*)&h;
}
__device__ __forceinline__ void st_h2(__half* p, float a, float b) {
    *(__half2*)p = __floats2half2_rn(a, b);
}

// ---------------------------------------------------------------------------
// Pre-convert: fp32 x + all weights -> fp16 scratch.
// ---------------------------------------------------------------------------
__global__ void __launch_bounds__(256)
preconv(const float4* __restrict__ x,
        const float4* __restrict__ wdq, const float4* __restrict__ wdkv,
        const float4* __restrict__ wkr, const float4* __restrict__ wuq,
        const float4* __restrict__ wqr, const float4* __restrict__ wuk,
        const float4* __restrict__ wuv, const float4* __restrict__ wo)
{
    int i = blockIdx.x * blockDim.x + threadIdx.x;
    const float4* s;
    __half* d;
    if (i < 2097152) {
        s = x + i;
        d = g_xh + (size_t)i * 4;
    } else {
        int j = i - 2097152;
        if (j >= 2523136) return;
        if      (j <  262144) s = wdq  + j;
        else if (j <  524288) s = wdkv + (j -  262144);
        else if (j <  557056) s = wkr  + (j -  524288);
        else if (j <  819200) s = wuq  + (j -  557056);
        else if (j <  950272) s = wqr  + (j -  819200);
        else if (j < 1212416) s = wuk  + (j -  950272);
        else if (j < 1474560) s = wuv  + (j - 1212416);
        else                  s = wo   + (j - 1474560);
        d = g_wh + (size_t)j * 4;
    }
    float4 v = *s;
    __half2 lo = __floats2half2_rn(v.x, v.y);
    __half2 hi = __floats2half2_rn(v.z, v.w);
    *(uint2*)d = make_uint2(*(unsigned*)&lo, *(unsigned*)&hi);
}

// ---------------------------------------------------------------------------
// 3-stage cp.async fp16 GEMM (m16n8k16 + ldmatrix), NT. 256 thr, 8 warps
// 4m x 2n, warp tile m32 x n64, K-tile 64 halfs. M fixed = 4096.
// MODE 0: float Cout ; MODE 5: x-proj split ; MODE 8: merged up-proj
// (q outputs pre-scaled by QSC).
// ---------------------------------------------------------------------------
#define KPW 36
#define STGW (2 * 128 * KPW)                 // 9216 words / stage
#define GEMM_SMEM_BYTES (3 * STGW * 4)       // 110592

template<int MODE>
__global__ void __launch_bounds__(256, 2)
gemmh(const __half* __restrict__ A0, const __half* __restrict__ A1, int aSplit,
      const __half* __restrict__ B0, const __half* __restrict__ B1,
      const __half* __restrict__ B2, const __half* __restrict__ B3,
      int nb1, int nb2, int nb3,
      int N, int K, int lda, int ldb,
      float* __restrict__ Cout, int ldc,
      const float* __restrict__ fc, const float* __restrict__ fs)
{
    extern __shared__ unsigned gsm[];
    const unsigned sG = (unsigned)__cvta_generic_to_shared(gsm);

    const int m0 = blockIdx.y * 128;
    const int n0 = blockIdx.x * 128;
    const __half* A = (n0 < aSplit) ? A0 : A1;

    const int tid  = threadIdx.x;
    const int wid  = tid >> 5;
    const int lane = tid & 31;
    const int g    = lane >> 2;
    const int tig  = lane & 3;
    const int wr   = (wid & 3) * 32;
    const int wc   = (wid >> 2) * 64;
    const int lrow = tid >> 3;          // 0..31
    const int lkh  = (tid & 7) * 8;     // half offset 0..56
    const int nk   = K / 64;

    const int la15 = lane & 15;
    const int aW   = (lane >> 4) * 4;
    const int bR   = ((lane >> 4) & 1) * 8 + (lane & 7);
    const int bW   = ((lane >> 3) & 1) * 4;

    float acc[2][8][4];
    #pragma unroll
    for (int i = 0; i < 2; i++)
        #pragma unroll
        for (int j = 0; j < 8; j++)
            #pragma unroll
            for (int r = 0; r < 4; r++) acc[i][j][r] = 0.f;

    auto issue = [&](int kt) {
        unsigned* SA = gsm + (kt % 3) * STGW;
        unsigned* SB = SA + 128 * KPW;
        #pragma unroll
        for (int i = 0; i < 4; i++) {
            int r = lrow + i * 32;
            cp16(SA + r * KPW + (lkh >> 1),
                 A + (size_t)(m0 + r) * lda + kt * 64 + lkh, true);
            int br = n0 + r;
            const __half* bp = (br < nb1) ? B0 + (size_t)br * ldb
                             : (br < nb2) ? B1 + (size_t)(br - nb1) * ldb
                             : (br < nb3) ? B2 + (size_t)(br - nb2) * ldb
                                          : B3 + (size_t)(br - nb3) * ldb;
            cp16(SB + r * KPW + (lkh >> 1), bp + kt * 64 + lkh, br < N);
        }
        asm volatile("cp.async.commit_group;\n" ::: "memory");
    };

    issue(0); issue(1);
    asm volatile("cp.async.wait_group 1;\n" ::: "memory");
    __syncthreads();

    for (int kt = 0; kt < nk; kt++) {
        if (kt + 2 < nk) issue(kt + 2);
        else asm volatile("cp.async.commit_group;\n" ::: "memory");

        const unsigned abase = sG + (unsigned)((kt % 3) * STGW) * 4u;
        const unsigned bbase = abase + 128u * KPW * 4u;
        #pragma unroll
        for (int kk = 0; kk < 4; kk++) {
            unsigned af[2][4];
            ldsm4(af[0], abase + (unsigned)(((wr      + la15) * KPW + kk * 8 + aW) * 4));
            ldsm4(af[1], abase + (unsigned)(((wr + 16 + la15) * KPW + kk * 8 + aW) * 4));
            #pragma unroll
            for (int jp = 0; jp < 4; jp++) {
                unsigned bfr[4];
                ldsm4(bfr, bbase + (unsigned)(((wc + jp * 16 + bR) * KPW + kk * 8 + bW) * 4));
                #pragma unroll
                for (int ti = 0; ti < 2; ti++) {
                    mma_f16(acc[ti][jp * 2    ], af[ti], bfr);
                    mma_f16(acc[ti][jp * 2 + 1], af[ti], bfr + 2);
                }
            }
        }
        asm volatile("cp.async.wait_group 1;\n" ::: "memory");
        __syncthreads();
    }

    #pragma unroll
    for (int ti = 0; ti < 2; ti++) {
        #pragma unroll
        for (int rh = 0; rh < 2; rh++) {
            int gm = m0 + wr + ti * 16 + g + rh * 8;
            int bb = gm >> 11;
            int tt = gm & (T_ - 1);
            #pragma unroll
            for (int tj = 0; tj < 8; tj++) {
                int gn = n0 + wc + tj * 8 + tig * 2;
                float v0 = acc[ti][tj][rh * 2 + 0];
                float v1 = acc[ti][tj][rh * 2 + 1];
                if (MODE == 0) {
                    if (gn < N)
                        *(float2*)(Cout + (size_t)gm * ldc + gn) = make_float2(v0, v1);
                } else if (MODE == 5) {
                    if (gn < 512) {
                        st_h2(g_cq + (size_t)gm * 512 + gn, v0, v1);
                    } else if (gn < 1024) {
                        st_h2(g_ckv + (size_t)gm * 512 + gn - 512, v0, v1);
                    } else if (gn < 1088) {
                        int j = gn - 1024;
                        int p = j >> 1;
                        float c = fc[tt * 32 + p], s = fs[tt * 32 + p];
                        float o0 = v0 * c - v1 * s;
                        float o1 = v0 * s + v1 * c;
                        #pragma unroll
                        for (int hh = 0; hh < H_; hh++)
                            st_h2(g_k + ((size_t)(bb * H_ + hh) * T_ + tt) * D_ + HS_ + j, o0, o1);
                    }
                } else if (MODE == 8) {
                    if (gn < 2048) {
                        int hh = gn >> 7, dd = gn & 127;
                        st_h2(g_q + ((size_t)(bb * H_ + hh) * T_ + tt) * D_ + dd,
                              v0 * QSC, v1 * QSC);
                    } else if (gn < 3072) {
                        int j2 = gn - 2048;
                        int hh = j2 >> 6, jj = j2 & 63;
                        int p = jj >> 1;
                        float c = fc[tt * 32 + p], s = fs[tt * 32 + p];
                        st_h2(g_q + ((size_t)(bb * H_ + hh) * T_ + tt) * D_ + HS_ + jj,
                              (v0 * c - v1 * s) * QSC, (v0 * s + v1 * c) * QSC);
                    } else if (gn < 5120) {
                        int t2 = gn - 3072;
                        int hh = t2 >> 7, dd = t2 & 127;
                        st_h2(g_k + ((size_t)(bb * H_ + hh) * T_ + tt) * D_ + dd, v0, v1);
                    } else {
                        int t3 = gn - 5120;
                        int hh = t3 >> 7, dd = t3 & 127;
                        __half* vp = g_v + ((size_t)(bb * H_ + hh) * HS_ + dd) * T_ + tt;
                        vp[0]  = __float2half(v0);
                        vp[T_] = __float2half(v1);
                    }
                }
            }
        }
    }
}

// ---------------------------------------------------------------------------
// Fused flash attention, fp16 (m16n8k16 + ldmatrix), fp32 log2-domain
// softmax, Q fragments in registers. Warp-level skip of fully-masked
// diagonal half-tiles; mask ALU only where the diagonal crosses the warp.
// ---------------------------------------------------------------------------
#define QPW  100
#define KPW2 100
#define VPW  36
#define PPW  36
#define FLASH_SMEM_WORDS (128*QPW + 64*KPW2 + 128*VPW + 128*PPW)  // 28416
#define FLASH_SMEM_BYTES (FLASH_SMEM_WORDS * 4)                   // 113664

__global__ void __launch_bounds__(256, 1)
flash_attn(const __half* __restrict__ qg, const __half* __restrict__ kg,
           const __half* __restrict__ vg, __half* __restrict__ ao)
{
    extern __shared__ unsigned smu[];
    unsigned* Qs = smu;
    unsigned* Ks = Qs + 128 * QPW;
    unsigned* Vs = Ks + 64 * KPW2;
    unsigned* Ps = Vs + 128 * VPW;
    const unsigned sQ = (unsigned)__cvta_generic_to_shared(Qs);
    const unsigned sK = (unsigned)__cvta_generic_to_shared(Ks);
    const unsigned sV = (unsigned)__cvta_generic_to_shared(Vs);
    const unsigned sP = (unsigned)__cvta_generic_to_shared(Ps);

    const int z  = blockIdx.x;
    const int iy = (int)gridDim.y - 1 - blockIdx.y;
    const int q0 = iy * 128;
    const int b = z / H_, h = z % H_;

    const __half* Qg = qg + (size_t)z * T_ * D_;
    const __half* Kg = kg + (size_t)z * T_ * D_;
    const __half* Vg = vg + (size_t)z * HS_ * T_;   // (d, t)

    const int tid = threadIdx.x;
    const int wid = tid >> 5, lane = tid & 31;
    const int g = lane >> 2, tig = lane & 3;
    const int qrow0 = q0 + wid * 16 + g;

    const int la15 = lane & 15;
    const int aW   = (lane >> 4) * 4;
    const int bR   = ((lane >> 4) & 1) * 8 + (lane & 7);
    const int bW   = ((lane >> 3) & 1) * 4;

    auto issueK = [&](int kt) {
        #pragma unroll
        for (int it = 0; it < 6; it++) {
            int idx = tid + it * 256;
            int row = idx / 24, kh = (idx % 24) * 8;
            cp16(Ks + row * KPW2 + (kh >> 1),
                 Kg + (size_t)(kt * 64 + row) * D_ + kh, true);
        }
        asm volatile("cp.async.commit_group;\n" ::: "memory");
    };
    auto issueV = [&](int kt) {
        #pragma unroll
        for (int it = 0; it < 4; it++) {
            int idx = tid + it * 256;
            int dd = idx / 8, kh = (idx % 8) * 8;
            cp16(Vs + dd * VPW + (kh >> 1),
                 Vg + (size_t)dd * T_ + kt * 64 + kh, true);
        }
        asm volatile("cp.async.commit_group;\n" ::: "memory");
    };

    #pragma unroll
    for (int it = 0; it < 12; it++) {
        int idx = tid + it * 256;
        int row = idx / 24, kh = (idx % 24) * 8;
        cp16(Qs + row * QPW + (kh >> 1),
             Qg + (size_t)(q0 + row) * D_ + kh, true);
    }
    issueK(0);      // commits Q + K0 as one group
    issueV(0);

    // Hoist Q fragments into registers
    asm volatile("cp.async.wait_group 1;\n" ::: "memory");
    __syncthreads();
    unsigned qf[12][4];
    #pragma unroll
    for (int kk = 0; kk < 12; kk++)
        ldsm4(qf[kk], sQ + (unsigned)(((wid * 16 + la15) * QPW + kk * 8 + aW) * 4));

    float m_i[2] = {-1e30f, -1e30f};
    float l_i[2] = {0.f, 0.f};
    float o[16][4];
    #pragma unroll
    for (int j = 0; j < 16; j++)
        #pragma unroll
        for (int r = 0; r < 4; r++) o[j][r] = 0.f;

    const int nkt = 2 * iy + 2;

    for (int kt = 0; kt < nkt; kt++) {
        asm volatile("cp.async.wait_group 1;\n" ::: "memory");  // K(kt) ready
        __syncthreads();

        // Warp-level tile classification against the causal diagonal:
        //  kt == 2iy   : warps 0-3 partially masked, warps 4-7 clean
        //  kt == 2iy+1 : warps 0-3 fully masked (skip), warps 4-7 partial
        const bool skipTile = (kt == 2 * iy + 1) && (wid < 4);
        const bool maskTile = ((kt == 2 * iy) && (wid < 4)) ||
                              ((kt == 2 * iy + 1) && (wid >= 4));

        if (!skipTile) {
            // S = Q K^T : m16 x n64, k=192 (12 x k16); Q in registers
            float s[8][4];
            #pragma unroll
            for (int j = 0; j < 8; j++)
                #pragma unroll
                for (int r = 0; r < 4; r++) s[j][r] = 0.f;

            #pragma unroll
            for (int kk = 0; kk < 12; kk++) {
                #pragma unroll
                for (int jp = 0; jp < 4; jp++) {
                    unsigned bfr[4];
                    ldsm4(bfr, sK + (unsigned)(((jp * 16 + bR) * KPW2 + kk * 8 + bW) * 4));
                    mma_f16(s[jp * 2    ], qf[kk], bfr);
                    mma_f16(s[jp * 2 + 1], qf[kk], bfr + 2);
                }
            }

            // Online softmax (log2 domain)
            #pragma unroll
            for (int r2 = 0; r2 < 2; r2++) {
                const int row = qrow0 + r2 * 8;
                float mx = -1e30f;
                #pragma unroll
                for (int j = 0; j < 8; j++) {
                    #pragma unroll
                    for (int c = 0; c < 2; c++) {
                        int r = r2 * 2 + c;
                        float v = s[j][r];
                        if (maskTile) {
                            int col = kt * 64 + j * 8 + 2 * tig + c;
                            if (col > row) v = -1e30f;
                        }
                        s[j][r] = v;
                        mx = fmaxf(mx, v);
                    }
                }
                mx = fmaxf(mx, __shfl_xor_sync(0xffffffffu, mx, 1));
                mx = fmaxf(mx, __shfl_xor_sync(0xffffffffu, mx, 2));
                float mnew = fmaxf(m_i[r2], mx);
                float alpha = exp2f(m_i[r2] - mnew);
                m_i[r2] = mnew;

                float ls = 0.f;
                #pragma unroll
                for (int j = 0; j < 8; j++) {
                    #pragma unroll
                    for (int c = 0; c < 2; c++) {
                        int r = r2 * 2 + c;
                        float p = exp2f(s[j][r] - mnew);
                        s[j][r] = p;
                        ls += p;
                    }
                }
                ls += __shfl_xor_sync(0xffffffffu, ls, 1);
                ls += __shfl_xor_sync(0xffffffffu, ls, 2);
                l_i[r2] = l_i[r2] * alpha + ls;

                #pragma unroll
                for (int j = 0; j < 16; j++) {
                    o[j][r2 * 2 + 0] *= alpha;
                    o[j][r2 * 2 + 1] *= alpha;
                }
            }

            // P -> smem (fp16 pairs, per-warp rows)
            {
                int base0 = (wid * 16 + g) * PPW;
                int base1 = (wid * 16 + g + 8) * PPW;
                #pragma unroll
                for (int j = 0; j < 8; j++) {
                    Ps[base0 + j * 4 + tig] = packh2(s[j][0], s[j][1]);
                    Ps[base1 + j * 4 + tig] = packh2(s[j][2], s[j][3]);
                }
            }
            __syncwarp();
        }

        asm volatile("cp.async.wait_group 0;\n" ::: "memory");  // V ready
        __syncthreads();                                        // done with K

        if (kt + 1 < nkt) issueK(kt + 1);
        else asm volatile("cp.async.commit_group;\n" ::: "memory");

        if (!skipTile) {
            // O += P V : m16 x n128, k=64 (4 x k16); V d-major
            #pragma unroll
            for (int kk = 0; kk < 4; kk++) {
                unsigned a[4];
                ldsm4(a, sP + (unsigned)(((wid * 16 + la15) * PPW + kk * 8 + aW) * 4));
                #pragma unroll
                for (int jp = 0; jp < 8; jp++) {
                    unsigned bfr[4];
                    ldsm4(bfr, sV + (unsigned)(((jp * 16 + bR) * VPW + kk * 8 + bW) * 4));
                    mma_f16(o[jp * 2    ], a, bfr);
                    mma_f16(o[jp * 2 + 1], a, bfr + 2);
                }
            }
        }

        __syncthreads();
        if (kt + 1 < nkt) issueV(kt + 1);
        else asm volatile("cp.async.commit_group;\n" ::: "memory");
    }

    const float inv0 = 1.f / l_i[0];
    const float inv1 = 1.f / l_i[1];
    #pragma unroll
    for (int j = 0; j < 16; j++) {
        int d = j * 8 + 2 * tig;
        size_t base0 = ((size_t)(b * T_ + qrow0    )) * C_ + h * HS_ + d;
        size_t base1 = ((size_t)(b * T_ + qrow0 + 8)) * C_ + h * HS_ + d;
        st_h2(ao + base0, o[j][0] * inv0, o[j][1] * inv0);
        st_h2(ao + base1, o[j][2] * inv1, o[j][3] * inv1);
    }
}

// ---------------------------------------------------------------------------
// Launch
// ---------------------------------------------------------------------------
extern "C" void kernel_launch(void* const* d_in, const int* in_sizes, int n_in,
                              void* d_out, int out_size)
{
    const float* x    = (const float*)d_in[0];
    const float* fc   = (const float*)d_in[1];
    const float* fs   = (const float*)d_in[2];
    const float* Wdq  = (const float*)d_in[3];
    const float* Wuq  = (const float*)d_in[4];
    const float* Wdkv = (const float*)d_in[5];
    const float* Wuk  = (const float*)d_in[6];
    const float* Wuv  = (const float*)d_in[7];
    const float* Wqr  = (const float*)d_in[8];
    const float* Wkr  = (const float*)d_in[9];
    const float* Wo   = (const float*)d_in[10];
    float* out = (float*)d_out;

    __half *xh, *wh, *cq, *ckv, *q, *k, *v, *ao;
    cudaGetSymbolAddress((void**)&xh,  g_xh);
    cudaGetSymbolAddress((void**)&wh,  g_wh);
    cudaGetSymbolAddress((void**)&cq,  g_cq);
    cudaGetSymbolAddress((void**)&ckv, g_ckv);
    cudaGetSymbolAddress((void**)&q,   g_q);
    cudaGetSymbolAddress((void**)&k,   g_k);
    cudaGetSymbolAddress((void**)&v,   g_v);
    cudaGetSymbolAddress((void**)&ao,  g_ao);

    static bool attr_set = false;
    if (!attr_set) {
        cudaFuncSetAttribute(flash_attn, cudaFuncAttributeMaxDynamicSharedMemorySize,
                             FLASH_SMEM_BYTES);
        cudaFuncSetAttribute(gemmh<0>, cudaFuncAttributeMaxDynamicSharedMemorySize,
                             GEMM_SMEM_BYTES);
        cudaFuncSetAttribute(gemmh<5>, cudaFuncAttributeMaxDynamicSharedMemorySize,
                             GEMM_SMEM_BYTES);
        cudaFuncSetAttribute(gemmh<8>, cudaFuncAttributeMaxDynamicSharedMemorySize,
                             GEMM_SMEM_BYTES);
        attr_set = true;
    }

    dim3 blk(256);
    const int HUGE = 1 << 29;

    // Convert x + weights to fp16
    preconv<<<(4620288 + 255) / 256, 256>>>(
        (const float4*)x, (const float4*)Wdq, (const float4*)Wdkv,
        (const float4*)Wkr, (const float4*)Wuq, (const float4*)Wqr,
        (const float4*)Wuk, (const float4*)Wuv, (const float4*)Wo);

    // GEMM A: x -> [c_q | c_kv | rope-bcast k_r], N=1088, K=2048
    gemmh<5><<<dim3(9, 32), blk, GEMM_SMEM_BYTES>>>(
        xh, xh, HUGE,
        wh + OFF_WDQ, wh + OFF_WDKV, wh + OFF_WKR, wh + OFF_WKR,
        512, 1024, 1088,
        1088, C_, C_, C_, nullptr, 0, fc, fs);

    // GEMM B+C merged: [cq|ckv] -> [q_c | rope q_r | k_c | v], N=7168, K=512
    gemmh<8><<<dim3(56, 32), blk, GEMM_SMEM_BYTES>>>(
        cq, ckv, 3072,
        wh + OFF_WUQ, wh + OFF_WQR, wh + OFF_WUK, wh + OFF_WUV,
        2048, 3072, 5120,
        7168, NLQ_, NLQ_, NLQ_, nullptr, 0, fc, fs);

    // Fused flash attention (fp16 operands, Q pre-scaled, diag warp-skip)
    dim3 gfa(B_ * H_, T_ / 128);
    flash_attn<<<gfa, 256, FLASH_SMEM_BYTES>>>(q, k, v, ao);

    // Output projection (fp16 in, fp32 out)
    gemmh<0><<<dim3(16, 32), blk, GEMM_SMEM_BYTES>>>(
        ao, ao, HUGE,
        wh + OFF_WO, wh + OFF_WO, wh + OFF_WO, wh + OFF_WO,
        HUGE, HUGE, HUGE,
        2048, C_, C_, C_, out, C_, fc, fs);
}